// round 1
// baseline (speedup 1.0000x reference)
#include <cuda_runtime.h>
#include <math.h>

#define Sdim 196
#define Bn   64
#define Cdim 1024
#define Hdim 1024
#define Edim 512
#define Vdim 32000
#define Tn   20
#define NSTEP (Tn - 1)

// ---------------- scratch (device globals; no runtime allocation) ------------
__device__ float g_ctx_proj[(size_t)Sdim * Bn * Cdim];   // [S*B, C]  ~51MB
__device__ float g_h[Bn * Hdim];
__device__ float g_hq[Bn * Cdim];
__device__ float g_scores[Sdim * Bn];
__device__ float g_alpha[Sdim * Bn];
__device__ float g_z[Bn * Cdim];
__device__ float g_xcat[Bn * (Edim + Cdim)];
__device__ float g_gi[Bn * 3 * Hdim];
__device__ float g_gh[Bn * 3 * Hdim];
__device__ float g_o1[Bn * Edim];
__device__ float g_o2[Bn * Edim];
__device__ float g_p[Bn * Edim];
__device__ float g_logits[(size_t)Bn * Vdim];            // 8.2MB
__device__ float g_nll[NSTEP * Bn];

// ---------------- block reductions (deterministic fixed order) ---------------
__device__ __forceinline__ float blockReduceSum(float v, float* red) {
    #pragma unroll
    for (int o = 16; o; o >>= 1) v += __shfl_xor_sync(0xffffffffu, v, o);
    if ((threadIdx.x & 31) == 0) red[threadIdx.x >> 5] = v;
    __syncthreads();
    float t = 0.f;
    int nw = blockDim.x >> 5;
    for (int i = 0; i < nw; i++) t += red[i];
    __syncthreads();
    return t;
}
__device__ __forceinline__ float blockReduceMax(float v, float* red) {
    #pragma unroll
    for (int o = 16; o; o >>= 1) v = fmaxf(v, __shfl_xor_sync(0xffffffffu, v, o));
    if ((threadIdx.x & 31) == 0) red[threadIdx.x >> 5] = v;
    __syncthreads();
    float t = red[0];
    int nw = blockDim.x >> 5;
    for (int i = 1; i < nw; i++) t = fmaxf(t, red[i]);
    __syncthreads();
    return t;
}

// ---------------- GEMMs: 64x64 tile, BK=32, 256 threads, 4x4/thread ----------
// C[M,N] = A[M,K] @ B[K,N]    (row-major everywhere). M,N mult of 64, K mult of 32.
__global__ void gemm_nn(const float* __restrict__ A, const float* __restrict__ B,
                        float* __restrict__ C, int M, int N, int K) {
    __shared__ float As[32][65];  // [k][m]
    __shared__ float Bs[32][65];  // [k][n]
    const int row0 = blockIdx.y * 64, col0 = blockIdx.x * 64;
    const int tid = threadIdx.x;
    const int tx = tid & 15, ty = tid >> 4;
    float acc[4][4] = {};
    for (int k0 = 0; k0 < K; k0 += 32) {
        #pragma unroll
        for (int i = 0; i < 8; i++) {
            int li = tid + i * 256;
            int m = li >> 5, k = li & 31;
            As[k][m] = A[(size_t)(row0 + m) * K + k0 + k];
        }
        #pragma unroll
        for (int i = 0; i < 8; i++) {
            int li = tid + i * 256;
            int k = li >> 6, n = li & 63;
            Bs[k][n] = B[(size_t)(k0 + k) * N + col0 + n];
        }
        __syncthreads();
        #pragma unroll
        for (int kk = 0; kk < 32; kk++) {
            float a[4], b[4];
            #pragma unroll
            for (int j = 0; j < 4; j++) a[j] = As[kk][ty * 4 + j];
            #pragma unroll
            for (int j = 0; j < 4; j++) b[j] = Bs[kk][tx * 4 + j];
            #pragma unroll
            for (int i2 = 0; i2 < 4; i2++)
                #pragma unroll
                for (int j = 0; j < 4; j++)
                    acc[i2][j] = fmaf(a[i2], b[j], acc[i2][j]);
        }
        __syncthreads();
    }
    #pragma unroll
    for (int i2 = 0; i2 < 4; i2++)
        #pragma unroll
        for (int j = 0; j < 4; j++)
            C[(size_t)(row0 + ty * 4 + i2) * N + col0 + tx * 4 + j] = acc[i2][j];
}

// C[M,N] = A[M,K] @ B[N,K]^T (+ optional bias[n]).
__global__ void gemm_nt(const float* __restrict__ A, const float* __restrict__ B,
                        const float* __restrict__ bias, float* __restrict__ C,
                        int M, int N, int K) {
    __shared__ float As[32][65];  // [k][m]
    __shared__ float Bs[32][65];  // [k][n]
    const int row0 = blockIdx.y * 64, col0 = blockIdx.x * 64;
    const int tid = threadIdx.x;
    const int tx = tid & 15, ty = tid >> 4;
    float acc[4][4] = {};
    for (int k0 = 0; k0 < K; k0 += 32) {
        #pragma unroll
        for (int i = 0; i < 8; i++) {
            int li = tid + i * 256;
            int m = li >> 5, k = li & 31;
            As[k][m] = A[(size_t)(row0 + m) * K + k0 + k];
        }
        #pragma unroll
        for (int i = 0; i < 8; i++) {
            int li = tid + i * 256;
            int n = li >> 5, k = li & 31;
            Bs[k][n] = B[(size_t)(col0 + n) * K + k0 + k];
        }
        __syncthreads();
        #pragma unroll
        for (int kk = 0; kk < 32; kk++) {
            float a[4], b[4];
            #pragma unroll
            for (int j = 0; j < 4; j++) a[j] = As[kk][ty * 4 + j];
            #pragma unroll
            for (int j = 0; j < 4; j++) b[j] = Bs[kk][tx * 4 + j];
            #pragma unroll
            for (int i2 = 0; i2 < 4; i2++)
                #pragma unroll
                for (int j = 0; j < 4; j++)
                    acc[i2][j] = fmaf(a[i2], b[j], acc[i2][j]);
        }
        __syncthreads();
    }
    #pragma unroll
    for (int i2 = 0; i2 < 4; i2++)
        #pragma unroll
        for (int j = 0; j < 4; j++) {
            int n = col0 + tx * 4 + j;
            float bv = bias ? bias[n] : 0.f;
            C[(size_t)(row0 + ty * 4 + i2) * N + n] = acc[i2][j] + bv;
        }
}

// ---------------- elementwise / reduction kernels ----------------------------
__global__ void k_zero_h() {
    g_h[blockIdx.x * 256 + threadIdx.x] = 0.f;
}

// scores[s,b] = sum_m tanh(ctx_proj[s,b,m] + hq[b,m]) * mlp[m]
__global__ void k_scores(const float* __restrict__ mlp) {
    const int sb = blockIdx.x;              // = s*Bn + b
    const int b = sb & (Bn - 1);
    const float* __restrict__ row = g_ctx_proj + (size_t)sb * Cdim;
    const float* __restrict__ hqr = g_hq + b * Cdim;
    __shared__ float red[8];
    float sum = 0.f;
    for (int m = threadIdx.x; m < Cdim; m += 256)
        sum += tanhf(row[m] + hqr[m]) * mlp[m];
    float tot = blockReduceSum(sum, red);
    if (threadIdx.x == 0) g_scores[sb] = tot;
}

// softmax over S for each b (one block per b)
__global__ void k_softmax() {
    const int b = blockIdx.x;
    const int s = threadIdx.x;
    __shared__ float red[8];
    float v = (s < Sdim) ? g_scores[s * Bn + b] : -1e30f;
    float mx = blockReduceMax(v, red);
    float e = (s < Sdim) ? expf(v - mx) : 0.f;
    float tot = blockReduceSum(e, red);
    if (s < Sdim) g_alpha[s * Bn + b] = e / tot;
}

// z[b,c] = sum_s alpha[s,b] * ctx[s,b,c]
__global__ void k_zvec(const float* __restrict__ ctx) {
    const int b = blockIdx.y;
    const int c = blockIdx.x * 256 + threadIdx.x;
    __shared__ float al[Sdim];
    for (int s = threadIdx.x; s < Sdim; s += 256) al[s] = g_alpha[s * Bn + b];
    __syncthreads();
    float sum = 0.f;
    #pragma unroll 4
    for (int s = 0; s < Sdim; s++)
        sum += al[s] * ctx[((size_t)s * Bn + b) * Cdim + c];
    g_z[b * Cdim + c] = sum;
}

// x = concat(emb_W[y[t]], z)  -> [B, E+C]
__global__ void k_xcat(const float* __restrict__ embW, const int* __restrict__ y, int t) {
    const int i = blockIdx.x * 256 + threadIdx.x;
    const int b = i / (Edim + Cdim), e = i - b * (Edim + Cdim);
    float v;
    if (e < Edim) v = embW[(size_t)y[t * Bn + b] * Edim + e];
    else          v = g_z[b * Cdim + (e - Edim)];
    g_xcat[i] = v;
}

// GRU gates; overwrites g_h with new hidden state
__global__ void k_gru(const float* __restrict__ b_ih, const float* __restrict__ b_hh) {
    const int i = blockIdx.x * 256 + threadIdx.x;   // Bn*Hdim
    const int b = i >> 10, j = i & (Hdim - 1);
    const float* gi = g_gi + b * 3 * Hdim;
    const float* gh = g_gh + b * 3 * Hdim;
    float ir = gi[j]            + b_ih[j];
    float iz = gi[Hdim + j]     + b_ih[Hdim + j];
    float in_ = gi[2 * Hdim + j] + b_ih[2 * Hdim + j];
    float hr = gh[j]            + b_hh[j];
    float hz = gh[Hdim + j]     + b_hh[Hdim + j];
    float hn = gh[2 * Hdim + j] + b_hh[2 * Hdim + j];
    float r  = 1.f / (1.f + expf(-(ir + hr)));
    float zz = 1.f / (1.f + expf(-(iz + hz)));
    float n  = tanhf(in_ + r * hn);
    float hold = g_h[i];
    g_h[i] = (1.f - zz) * n + zz * hold;
}

// p = tanh( tanh(o1 + h2o_b) + y_emb + o2 + octx_b )
__global__ void k_pvec(const float* __restrict__ embW, const int* __restrict__ y,
                       const float* __restrict__ h2o_b, const float* __restrict__ octx_b, int t) {
    const int i = blockIdx.x * 256 + threadIdx.x;   // Bn*Edim
    const int b = i >> 9, e = i & (Edim - 1);
    float l = tanhf(g_o1[i] + h2o_b[e]);
    l += embW[(size_t)y[t * Bn + b] * Edim + e];
    l += g_o2[i] + octx_b[e];
    g_p[i] = tanhf(l);
}

// per-(t,b) NLL with log-sum-exp over V (logits already include bias)
__global__ void k_nll(const int* __restrict__ y, int t) {
    const int b = blockIdx.x;
    const float* __restrict__ row = g_logits + (size_t)b * Vdim;
    __shared__ float red[8];
    float m = -1e30f;
    for (int v = threadIdx.x; v < Vdim; v += 256) m = fmaxf(m, row[v]);
    float mx = blockReduceMax(m, red);
    float s = 0.f;
    for (int v = threadIdx.x; v < Vdim; v += 256) s += expf(row[v] - mx);
    float tot = blockReduceSum(s, red);
    if (threadIdx.x == 0) {
        int tgt = y[(t + 1) * Bn + b];
        float lse = mx + logf(tot);
        g_nll[t * Bn + b] = (tgt != 0) ? (lse - row[tgt]) : 0.f;
    }
}

__global__ void k_final(float* __restrict__ out) {
    __shared__ float red[8];
    float s = 0.f;
    for (int i = threadIdx.x; i < NSTEP * Bn; i += 256) s += g_nll[i];
    float tot = blockReduceSum(s, red);
    if (threadIdx.x == 0) out[0] = tot;
}

// ---------------- launch ------------------------------------------------------
extern "C" void kernel_launch(void* const* d_in, const int* in_sizes, int n_in,
                              void* d_out, int out_size) {
    const float* ctx         = (const float*)d_in[0];
    const int*   y           = (const int*)  d_in[1];
    const float* embW        = (const float*)d_in[2];
    const float* att_ctx2ctx = (const float*)d_in[3];
    const float* att_hid2ctx = (const float*)d_in[4];
    const float* att_mlp     = (const float*)d_in[5];
    const float* gru_W_ih    = (const float*)d_in[6];
    const float* gru_b_ih    = (const float*)d_in[7];
    const float* gru_W_hh    = (const float*)d_in[8];
    const float* gru_b_hh    = (const float*)d_in[9];
    const float* h2o_W       = (const float*)d_in[10];
    const float* h2o_b       = (const float*)d_in[11];
    const float* octx_W      = (const float*)d_in[12];
    const float* octx_b      = (const float*)d_in[13];
    const float* o2p_W       = (const float*)d_in[14];
    const float* o2p_b       = (const float*)d_in[15];

    float *p_ctxproj, *p_h, *p_hq, *p_z, *p_xcat, *p_gi, *p_gh, *p_o1, *p_o2, *p_p, *p_logits;
    cudaGetSymbolAddress((void**)&p_ctxproj, g_ctx_proj);
    cudaGetSymbolAddress((void**)&p_h,       g_h);
    cudaGetSymbolAddress((void**)&p_hq,      g_hq);
    cudaGetSymbolAddress((void**)&p_z,       g_z);
    cudaGetSymbolAddress((void**)&p_xcat,    g_xcat);
    cudaGetSymbolAddress((void**)&p_gi,      g_gi);
    cudaGetSymbolAddress((void**)&p_gh,      g_gh);
    cudaGetSymbolAddress((void**)&p_o1,      g_o1);
    cudaGetSymbolAddress((void**)&p_o2,      g_o2);
    cudaGetSymbolAddress((void**)&p_p,       g_p);
    cudaGetSymbolAddress((void**)&p_logits,  g_logits);

    // Precompute ctx_proj = ctx @ att_ctx2ctx   [S*B, C]
    gemm_nn<<<dim3(Cdim / 64, (Sdim * Bn) / 64), 256>>>(ctx, att_ctx2ctx, p_ctxproj,
                                                        Sdim * Bn, Cdim, Cdim);
    k_zero_h<<<(Bn * Hdim) / 256, 256>>>();

    for (int t = 0; t < NSTEP; t++) {
        // hq = h @ att_hid2ctx
        gemm_nn<<<dim3(Cdim / 64, 1), 256>>>(p_h, att_hid2ctx, p_hq, Bn, Cdim, Hdim);
        k_scores<<<Sdim * Bn, 256>>>(att_mlp);
        k_softmax<<<Bn, 256>>>();
        k_zvec<<<dim3(Cdim / 256, Bn), 256>>>(ctx);
        k_xcat<<<(Bn * (Edim + Cdim)) / 256, 256>>>(embW, y, t);
        // gi = x @ W_ih^T ; gh = h @ W_hh^T
        gemm_nt<<<dim3((3 * Hdim) / 64, 1), 256>>>(p_xcat, gru_W_ih, (const float*)nullptr,
                                                   p_gi, Bn, 3 * Hdim, Edim + Cdim);
        gemm_nt<<<dim3((3 * Hdim) / 64, 1), 256>>>(p_h, gru_W_hh, (const float*)nullptr,
                                                   p_gh, Bn, 3 * Hdim, Hdim);
        k_gru<<<(Bn * Hdim) / 256, 256>>>(gru_b_ih, gru_b_hh);
        // o1 = ht @ hid2out_W^T ; o2 = z @ out_ctx_W^T
        gemm_nt<<<dim3(Edim / 64, 1), 256>>>(p_h, h2o_W, (const float*)nullptr,
                                             p_o1, Bn, Edim, Hdim);
        gemm_nt<<<dim3(Edim / 64, 1), 256>>>(p_z, octx_W, (const float*)nullptr,
                                             p_o2, Bn, Edim, Cdim);
        k_pvec<<<(Bn * Edim) / 256, 256>>>(embW, y, h2o_b, octx_b, t);
        // logits = p @ out2prob_W^T + b
        gemm_nt<<<dim3(Vdim / 64, 1), 256>>>(p_p, o2p_W, o2p_b,
                                             p_logits, Bn, Vdim, Edim);
        k_nll<<<Bn, 256>>>(y, t);
    }
    k_final<<<1, 256>>>((float*)d_out);
}

// round 2
// speedup vs baseline: 1.9468x; 1.9468x over previous
#include <cuda_runtime.h>
#include <math.h>

#define Sdim 196
#define Bn   64
#define Cdim 1024
#define Hdim 1024
#define Edim 512
#define Vdim 32000
#define NSTEP 19

// ---------------- scratch (device globals) -----------------------------------
__device__ float g_ctx_proj[(size_t)Sdim * Bn * Cdim];   // ~51MB
__device__ float g_h[Bn * Hdim];
__device__ float g_hq_part[4 * Bn * Cdim];
__device__ float g_hq[Bn * Cdim];
__device__ float g_scores[Sdim * Bn];
__device__ float g_alpha[Sdim * Bn];
__device__ float g_z[Bn * Cdim];
__device__ float g_xcat[Bn * (Edim + Cdim)];
__device__ float g_gi_part[6 * Bn * 3 * Hdim];
__device__ float g_gh_part[4 * Bn * 3 * Hdim];
__device__ float g_o1_part[4 * Bn * Edim];
__device__ float g_o2_part[4 * Bn * Edim];
__device__ float g_p[Bn * Edim];
__device__ float g_logits[(size_t)Bn * Vdim];
__device__ float g_nll[NSTEP * Bn];

// ---------------- fast math ---------------------------------------------------
__device__ __forceinline__ float ftanh(float x) {
    float xc = fminf(fmaxf(x, -15.f), 15.f);
    float e = __expf(2.f * xc);
    return __fdividef(e - 1.f, e + 1.f);
}
__device__ __forceinline__ float fsig(float x) {
    return __fdividef(1.f, 1.f + __expf(-x));
}

// ---------------- block reductions (fixed order) ------------------------------
__device__ __forceinline__ float blockReduceSum(float v, float* red) {
    #pragma unroll
    for (int o = 16; o; o >>= 1) v += __shfl_xor_sync(0xffffffffu, v, o);
    if ((threadIdx.x & 31) == 0) red[threadIdx.x >> 5] = v;
    __syncthreads();
    float t = 0.f;
    int nw = blockDim.x >> 5;
    for (int i = 0; i < nw; i++) t += red[i];
    __syncthreads();
    return t;
}
__device__ __forceinline__ float blockReduceMax(float v, float* red) {
    #pragma unroll
    for (int o = 16; o; o >>= 1) v = fmaxf(v, __shfl_xor_sync(0xffffffffu, v, o));
    if ((threadIdx.x & 31) == 0) red[threadIdx.x >> 5] = v;
    __syncthreads();
    float t = red[0];
    int nw = blockDim.x >> 5;
    for (int i = 1; i < nw; i++) t = fmaxf(t, red[i]);
    __syncthreads();
    return t;
}

// ============ big SGEMM: C[M,N] = A[M,K]@B[K,N], 128x128x16, 256 thr, 8x8 =====
__global__ __launch_bounds__(256) void gemm_big_nn(
    const float* __restrict__ A, const float* __restrict__ B,
    float* __restrict__ C, int M, int N, int K) {
    __shared__ float As[16][132];
    __shared__ float Bs[16][132];
    const int row0 = blockIdx.y * 128, col0 = blockIdx.x * 128;
    const int tid = threadIdx.x;
    const int tx = tid & 15, ty = tid >> 4;
    const int am = tid >> 1, aak = (tid & 1) * 8;
    const int bk = tid >> 4, bn = (tid & 15) * 8;
    float acc[8][8] = {};
    for (int k0 = 0; k0 < K; k0 += 16) {
        float4 a0 = *(const float4*)&A[(size_t)(row0 + am) * K + k0 + aak];
        float4 a1 = *(const float4*)&A[(size_t)(row0 + am) * K + k0 + aak + 4];
        As[aak + 0][am] = a0.x; As[aak + 1][am] = a0.y;
        As[aak + 2][am] = a0.z; As[aak + 3][am] = a0.w;
        As[aak + 4][am] = a1.x; As[aak + 5][am] = a1.y;
        As[aak + 6][am] = a1.z; As[aak + 7][am] = a1.w;
        *(float4*)&Bs[bk][bn]     = *(const float4*)&B[(size_t)(k0 + bk) * N + col0 + bn];
        *(float4*)&Bs[bk][bn + 4] = *(const float4*)&B[(size_t)(k0 + bk) * N + col0 + bn + 4];
        __syncthreads();
        #pragma unroll
        for (int kk = 0; kk < 16; kk++) {
            float a[8], b[8];
            *(float4*)&a[0] = *(const float4*)&As[kk][ty * 8];
            *(float4*)&a[4] = *(const float4*)&As[kk][ty * 8 + 4];
            *(float4*)&b[0] = *(const float4*)&Bs[kk][tx * 8];
            *(float4*)&b[4] = *(const float4*)&Bs[kk][tx * 8 + 4];
            #pragma unroll
            for (int i = 0; i < 8; i++)
                #pragma unroll
                for (int j = 0; j < 8; j++)
                    acc[i][j] = fmaf(a[i], b[j], acc[i][j]);
        }
        __syncthreads();
    }
    #pragma unroll
    for (int i = 0; i < 8; i++) {
        float* cr = &C[(size_t)(row0 + ty * 8 + i) * N + col0 + tx * 8];
        *(float4*)&cr[0] = make_float4(acc[i][0], acc[i][1], acc[i][2], acc[i][3]);
        *(float4*)&cr[4] = make_float4(acc[i][4], acc[i][5], acc[i][6], acc[i][7]);
    }
}

// ============ skinny NT GEMM with split-K (+ dual-problem batching) ===========
// C[64,N] = A[64,K] @ B[N,K]^T, tile 64x128x16, partial per blockIdx.z chunk.
// blockIdx.y selects problem (A0,B0,C0) or (A1,B1,C1).
__global__ __launch_bounds__(256) void gemm64_nt(
    const float* __restrict__ A0, const float* __restrict__ B0, float* __restrict__ C0,
    const float* __restrict__ A1, const float* __restrict__ B1, float* __restrict__ C1,
    int N, int K, int kChunk) {
    const float* A = A0; const float* B = B0; float* C = C0;
    if (blockIdx.y == 1) { A = A1; B = B1; C = C1; }
    __shared__ float As[16][68];
    __shared__ float Bs[16][132];
    const int col0 = blockIdx.x * 128;
    const int k0 = blockIdx.z * kChunk;
    const int tid = threadIdx.x;
    const int tx = tid & 15, ty = tid >> 4;
    const int lr = tid >> 2, lk = (tid & 3) * 4;
    float acc[4][8] = {};
    for (int kt = 0; kt < kChunk; kt += 16) {
        float4 a4 = *(const float4*)&A[(size_t)lr * K + k0 + kt + lk];
        As[lk + 0][lr] = a4.x; As[lk + 1][lr] = a4.y;
        As[lk + 2][lr] = a4.z; As[lk + 3][lr] = a4.w;
        #pragma unroll
        for (int i = 0; i < 2; i++) {
            int n = lr + i * 64;
            float4 b4 = *(const float4*)&B[(size_t)(col0 + n) * K + k0 + kt + lk];
            Bs[lk + 0][n] = b4.x; Bs[lk + 1][n] = b4.y;
            Bs[lk + 2][n] = b4.z; Bs[lk + 3][n] = b4.w;
        }
        __syncthreads();
        #pragma unroll
        for (int kk = 0; kk < 16; kk++) {
            float a[4], b[8];
            *(float4*)&a[0] = *(const float4*)&As[kk][ty * 4];
            *(float4*)&b[0] = *(const float4*)&Bs[kk][tx * 8];
            *(float4*)&b[4] = *(const float4*)&Bs[kk][tx * 8 + 4];
            #pragma unroll
            for (int i = 0; i < 4; i++)
                #pragma unroll
                for (int j = 0; j < 8; j++)
                    acc[i][j] = fmaf(a[i], b[j], acc[i][j]);
        }
        __syncthreads();
    }
    float* Cp = C + (size_t)blockIdx.z * 64 * N;
    #pragma unroll
    for (int i = 0; i < 4; i++) {
        float* cr = &Cp[(size_t)(ty * 4 + i) * N + col0 + tx * 8];
        *(float4*)&cr[0] = make_float4(acc[i][0], acc[i][1], acc[i][2], acc[i][3]);
        *(float4*)&cr[4] = make_float4(acc[i][4], acc[i][5], acc[i][6], acc[i][7]);
    }
}

// ============ skinny NN GEMM with split-K: C[64,N] = A[64,K] @ B[K,N] =========
__global__ __launch_bounds__(256) void gemm64_nn(
    const float* __restrict__ A, const float* __restrict__ B, float* __restrict__ C,
    int N, int K, int kChunk) {
    __shared__ float As[16][68];
    __shared__ float Bs[16][132];
    const int col0 = blockIdx.x * 128;
    const int k0 = blockIdx.z * kChunk;
    const int tid = threadIdx.x;
    const int tx = tid & 15, ty = tid >> 4;
    const int lr = tid >> 2, lk = (tid & 3) * 4;
    const int bk = tid >> 4, bn = (tid & 15) * 8;
    float acc[4][8] = {};
    for (int kt = 0; kt < kChunk; kt += 16) {
        float4 a4 = *(const float4*)&A[(size_t)lr * K + k0 + kt + lk];
        As[lk + 0][lr] = a4.x; As[lk + 1][lr] = a4.y;
        As[lk + 2][lr] = a4.z; As[lk + 3][lr] = a4.w;
        *(float4*)&Bs[bk][bn]     = *(const float4*)&B[(size_t)(k0 + kt + bk) * N + col0 + bn];
        *(float4*)&Bs[bk][bn + 4] = *(const float4*)&B[(size_t)(k0 + kt + bk) * N + col0 + bn + 4];
        __syncthreads();
        #pragma unroll
        for (int kk = 0; kk < 16; kk++) {
            float a[4], b[8];
            *(float4*)&a[0] = *(const float4*)&As[kk][ty * 4];
            *(float4*)&b[0] = *(const float4*)&Bs[kk][tx * 8];
            *(float4*)&b[4] = *(const float4*)&Bs[kk][tx * 8 + 4];
            #pragma unroll
            for (int i = 0; i < 4; i++)
                #pragma unroll
                for (int j = 0; j < 8; j++)
                    acc[i][j] = fmaf(a[i], b[j], acc[i][j]);
        }
        __syncthreads();
    }
    float* Cp = C + (size_t)blockIdx.z * 64 * N;
    #pragma unroll
    for (int i = 0; i < 4; i++) {
        float* cr = &Cp[(size_t)(ty * 4 + i) * N + col0 + tx * 8];
        *(float4*)&cr[0] = make_float4(acc[i][0], acc[i][1], acc[i][2], acc[i][3]);
        *(float4*)&cr[4] = make_float4(acc[i][4], acc[i][5], acc[i][6], acc[i][7]);
    }
}

// ---------------- elementwise / reduction kernels -----------------------------
__global__ void k_zero_h() { g_h[blockIdx.x * 256 + threadIdx.x] = 0.f; }

__global__ void k_hq_red() {
    int i = blockIdx.x * 256 + threadIdx.x;   // Bn*Cdim
    g_hq[i] = g_hq_part[i] + g_hq_part[Bn * Cdim + i]
            + g_hq_part[2 * Bn * Cdim + i] + g_hq_part[3 * Bn * Cdim + i];
}

// scores[s,b] = sum_m tanh(ctx_proj[s,b,m] + hq[b,m]) * mlp[m]
__global__ __launch_bounds__(256) void k_scores(const float* __restrict__ mlp) {
    const int sb = blockIdx.x;
    const int b = sb & (Bn - 1);
    const float* __restrict__ row = g_ctx_proj + (size_t)sb * Cdim;
    const float* __restrict__ hqr = g_hq + b * Cdim;
    __shared__ float red[8];
    const int m4 = threadIdx.x * 4;
    float4 r = *(const float4*)&row[m4];
    float4 h = *(const float4*)&hqr[m4];
    float4 w = *(const float4*)&mlp[m4];
    float sum = ftanh(r.x + h.x) * w.x + ftanh(r.y + h.y) * w.y
              + ftanh(r.z + h.z) * w.z + ftanh(r.w + h.w) * w.w;
    float tot = blockReduceSum(sum, red);
    if (threadIdx.x == 0) g_scores[sb] = tot;
}

__global__ void k_softmax() {
    const int b = blockIdx.x;
    const int s = threadIdx.x;
    __shared__ float red[8];
    float v = (s < Sdim) ? g_scores[s * Bn + b] : -1e30f;
    float mx = blockReduceMax(v, red);
    float e = (s < Sdim) ? __expf(v - mx) : 0.f;
    float tot = blockReduceSum(e, red);
    if (s < Sdim) g_alpha[s * Bn + b] = __fdividef(e, tot);
}

// z[b,c] = sum_s alpha[s,b] * ctx[s,b,c]   (float4 over c)
__global__ __launch_bounds__(128) void k_zvec(const float* __restrict__ ctx) {
    const int b = blockIdx.y;
    const int c4 = (blockIdx.x * 128 + threadIdx.x) * 4;
    __shared__ float al[Sdim];
    for (int s = threadIdx.x; s < Sdim; s += 128) al[s] = g_alpha[s * Bn + b];
    __syncthreads();
    float4 sum = make_float4(0.f, 0.f, 0.f, 0.f);
    #pragma unroll 4
    for (int s = 0; s < Sdim; s++) {
        float a = al[s];
        float4 v = *(const float4*)&ctx[((size_t)s * Bn + b) * Cdim + c4];
        sum.x = fmaf(a, v.x, sum.x); sum.y = fmaf(a, v.y, sum.y);
        sum.z = fmaf(a, v.z, sum.z); sum.w = fmaf(a, v.w, sum.w);
    }
    *(float4*)&g_z[b * Cdim + c4] = sum;
}

__global__ void k_xcat(const float* __restrict__ embW, const int* __restrict__ y, int t) {
    const int i = blockIdx.x * 256 + threadIdx.x;
    const int b = i / (Edim + Cdim), e = i - b * (Edim + Cdim);
    float v;
    if (e < Edim) v = embW[(size_t)y[t * Bn + b] * Edim + e];
    else          v = g_z[b * Cdim + (e - Edim)];
    g_xcat[i] = v;
}

// GRU: consumes split-K partials of gi (6) and gh (4), fixed-order sums.
__global__ void k_gru(const float* __restrict__ b_ih, const float* __restrict__ b_hh) {
    const int i = blockIdx.x * 256 + threadIdx.x;   // Bn*Hdim
    const int b = i >> 10, j = i & (Hdim - 1);
    float ir = b_ih[j], iz = b_ih[Hdim + j], in_ = b_ih[2 * Hdim + j];
    #pragma unroll
    for (int p = 0; p < 6; p++) {
        const float* g = g_gi_part + ((size_t)p * Bn + b) * 3 * Hdim;
        ir += g[j]; iz += g[Hdim + j]; in_ += g[2 * Hdim + j];
    }
    float hr = b_hh[j], hz = b_hh[Hdim + j], hn = b_hh[2 * Hdim + j];
    #pragma unroll
    for (int p = 0; p < 4; p++) {
        const float* g = g_gh_part + ((size_t)p * Bn + b) * 3 * Hdim;
        hr += g[j]; hz += g[Hdim + j]; hn += g[2 * Hdim + j];
    }
    float r  = fsig(ir + hr);
    float zz = fsig(iz + hz);
    float n  = ftanh(in_ + r * hn);
    float hold = g_h[i];
    g_h[i] = (1.f - zz) * n + zz * hold;
}

// p = tanh( tanh(o1 + h2o_b) + y_emb + o2 + octx_b )  (o1/o2 from partials)
__global__ void k_pvec(const float* __restrict__ embW, const int* __restrict__ y,
                       const float* __restrict__ h2o_b, const float* __restrict__ octx_b, int t) {
    const int i = blockIdx.x * 256 + threadIdx.x;   // Bn*Edim
    const int b = i >> 9, e = i & (Edim - 1);
    float o1 = h2o_b[e], o2 = octx_b[e];
    #pragma unroll
    for (int p = 0; p < 4; p++) {
        o1 += g_o1_part[p * Bn * Edim + i];
        o2 += g_o2_part[p * Bn * Edim + i];
    }
    float l = ftanh(o1);
    l += embW[(size_t)y[t * Bn + b] * Edim + e];
    l += o2;
    g_p[i] = ftanh(l);
}

// per-(t,b) NLL with LSE over V (bias folded in here)
__global__ __launch_bounds__(512) void k_nll(const int* __restrict__ y,
                                             const float* __restrict__ bias, int t) {
    const int b = blockIdx.x;
    const float* __restrict__ row = g_logits + (size_t)b * Vdim;
    __shared__ float red[16];
    float m = -1e30f;
    for (int v = threadIdx.x; v < Vdim; v += 512) m = fmaxf(m, row[v] + bias[v]);
    float mx = blockReduceMax(m, red);
    float s = 0.f;
    for (int v = threadIdx.x; v < Vdim; v += 512) s += __expf(row[v] + bias[v] - mx);
    float tot = blockReduceSum(s, red);
    if (threadIdx.x == 0) {
        int tgt = y[(t + 1) * Bn + b];
        float lse = mx + logf(tot);
        g_nll[t * Bn + b] = (tgt != 0) ? (lse - (row[tgt] + bias[tgt])) : 0.f;
    }
}

__global__ void k_final(float* __restrict__ out) {
    __shared__ float red[8];
    float s = 0.f;
    for (int i = threadIdx.x; i < NSTEP * Bn; i += 256) s += g_nll[i];
    float tot = blockReduceSum(s, red);
    if (threadIdx.x == 0) out[0] = tot;
}

// ---------------- launch ------------------------------------------------------
extern "C" void kernel_launch(void* const* d_in, const int* in_sizes, int n_in,
                              void* d_out, int out_size) {
    const float* ctx         = (const float*)d_in[0];
    const int*   y           = (const int*)  d_in[1];
    const float* embW        = (const float*)d_in[2];
    const float* att_ctx2ctx = (const float*)d_in[3];
    const float* att_hid2ctx = (const float*)d_in[4];
    const float* att_mlp     = (const float*)d_in[5];
    const float* gru_W_ih    = (const float*)d_in[6];
    const float* gru_b_ih    = (const float*)d_in[7];
    const float* gru_W_hh    = (const float*)d_in[8];
    const float* gru_b_hh    = (const float*)d_in[9];
    const float* h2o_W       = (const float*)d_in[10];
    const float* h2o_b       = (const float*)d_in[11];
    const float* octx_W      = (const float*)d_in[12];
    const float* octx_b      = (const float*)d_in[13];
    const float* o2p_W       = (const float*)d_in[14];
    const float* o2p_b       = (const float*)d_in[15];

    float *p_ctxproj, *p_h, *p_hqp, *p_z, *p_xcat, *p_gip, *p_ghp, *p_o1p, *p_o2p, *p_p, *p_logits;
    cudaGetSymbolAddress((void**)&p_ctxproj, g_ctx_proj);
    cudaGetSymbolAddress((void**)&p_h,       g_h);
    cudaGetSymbolAddress((void**)&p_hqp,     g_hq_part);
    cudaGetSymbolAddress((void**)&p_z,       g_z);
    cudaGetSymbolAddress((void**)&p_xcat,    g_xcat);
    cudaGetSymbolAddress((void**)&p_gip,     g_gi_part);
    cudaGetSymbolAddress((void**)&p_ghp,     g_gh_part);
    cudaGetSymbolAddress((void**)&p_o1p,     g_o1_part);
    cudaGetSymbolAddress((void**)&p_o2p,     g_o2_part);
    cudaGetSymbolAddress((void**)&p_p,       g_p);
    cudaGetSymbolAddress((void**)&p_logits,  g_logits);

    // ctx_proj = ctx @ att_ctx2ctx  [12544, 1024]
    gemm_big_nn<<<dim3(Cdim / 128, (Sdim * Bn) / 128), 256>>>(
        ctx, att_ctx2ctx, p_ctxproj, Sdim * Bn, Cdim, Cdim);
    k_zero_h<<<(Bn * Hdim) / 256, 256>>>();

    for (int t = 0; t < NSTEP; t++) {
        // hq = h @ att_hid2ctx  (split-K 4)
        gemm64_nn<<<dim3(Cdim / 128, 1, 4), 256>>>(p_h, att_hid2ctx, p_hqp,
                                                   Cdim, Hdim, Hdim / 4);
        k_hq_red<<<(Bn * Cdim) / 256, 256>>>();
        k_scores<<<Sdim * Bn, 256>>>(att_mlp);
        k_softmax<<<Bn, 256>>>();
        k_zvec<<<dim3(2, Bn), 128>>>(ctx);
        k_xcat<<<(Bn * (Edim + Cdim)) / 256, 256>>>(embW, y, t);
        // gi = xcat @ W_ih^T (split-K 6);  gh = h @ W_hh^T (split-K 4)
        gemm64_nt<<<dim3((3 * Hdim) / 128, 1, 6), 256>>>(
            p_xcat, gru_W_ih, p_gip, p_xcat, gru_W_ih, p_gip,
            3 * Hdim, Edim + Cdim, (Edim + Cdim) / 6);
        gemm64_nt<<<dim3((3 * Hdim) / 128, 1, 4), 256>>>(
            p_h, gru_W_hh, p_ghp, p_h, gru_W_hh, p_ghp,
            3 * Hdim, Hdim, Hdim / 4);
        k_gru<<<(Bn * Hdim) / 256, 256>>>(gru_b_ih, gru_b_hh);
        // o1 = h @ h2o_W^T, o2 = z @ octx_W^T  (dual, split-K 4)
        gemm64_nt<<<dim3(Edim / 128, 2, 4), 256>>>(
            p_h, h2o_W, p_o1p, p_z, octx_W, p_o2p,
            Edim, Hdim, Hdim / 4);
        k_pvec<<<(Bn * Edim) / 256, 256>>>(embW, y, h2o_b, octx_b, t);
        // logits = p @ out2prob_W^T  (bias folded into k_nll)
        gemm64_nt<<<dim3(Vdim / 128, 1, 1), 256>>>(
            p_p, o2p_W, p_logits, p_p, o2p_W, p_logits,
            Vdim, Edim, Edim);
        k_nll<<<Bn, 512>>>(y, o2p_b, t);
    }
    k_final<<<1, 256>>>((float*)d_out);
}

// round 4
// speedup vs baseline: 2.0439x; 1.0499x over previous
#include <cuda_runtime.h>
#include <cuda_bf16.h>
#include <math.h>

#define Sdim 196
#define Bn   64
#define Cdim 1024
#define Hdim 1024
#define Edim 512
#define Vdim 32000
#define NSTEP 19

// ---------------- scratch (device globals) -----------------------------------
__device__ float g_ctx_proj[(size_t)Sdim * Bn * Cdim];   // ~51MB
__device__ float g_WctxT[Cdim * Cdim];                   // att_ctx2ctx^T
__device__ float g_WhidT[Hdim * Cdim];                   // att_hid2ctx^T
__device__ __nv_bfloat16 g_Wo2p_bf16[(size_t)Vdim * Edim];
__device__ __nv_bfloat16 g_p_bf16[Bn * Edim];
__device__ float g_h[Bn * Hdim];
__device__ float g_hq[Bn * Cdim];
__device__ float g_scores[Sdim * Bn];
__device__ float g_z[Bn * Cdim];
__device__ float g_gi[Bn * 3 * Hdim];
__device__ float g_gh[Bn * 3 * Hdim];
__device__ float g_o1[Bn * Edim];
__device__ float g_o2[Bn * Edim];
__device__ float g_logits[(size_t)Bn * Vdim];
__device__ float g_nll[NSTEP * Bn];

// ---------------- fast math ---------------------------------------------------
__device__ __forceinline__ float ftanh(float x) {
    float xc = fminf(fmaxf(x, -15.f), 15.f);
    float e = __expf(2.f * xc);
    return __fdividef(e - 1.f, e + 1.f);
}
__device__ __forceinline__ float fsig(float x) {
    return __fdividef(1.f, 1.f + __expf(-x));
}
__device__ __forceinline__ float to_tf32(float x) {
    unsigned u;
    asm("cvt.rna.tf32.f32 %0, %1;" : "=r"(u) : "f"(x));
    return __uint_as_float(u);
}
__device__ __forceinline__ void mma_tf32(float* d, const float* a4, const float* b2) {
    asm volatile(
        "mma.sync.aligned.m16n8k8.row.col.f32.tf32.tf32.f32 "
        "{%0,%1,%2,%3}, {%4,%5,%6,%7}, {%8,%9}, {%0,%1,%2,%3};\n"
        : "+f"(d[0]), "+f"(d[1]), "+f"(d[2]), "+f"(d[3])
        : "r"(__float_as_uint(a4[0])), "r"(__float_as_uint(a4[1])),
          "r"(__float_as_uint(a4[2])), "r"(__float_as_uint(a4[3])),
          "r"(__float_as_uint(b2[0])), "r"(__float_as_uint(b2[1])));
}
__device__ __forceinline__ void mma_bf16(float* d, const unsigned* a4, const unsigned* b2) {
    asm volatile(
        "mma.sync.aligned.m16n8k16.row.col.f32.bf16.bf16.f32 "
        "{%0,%1,%2,%3}, {%4,%5,%6,%7}, {%8,%9}, {%0,%1,%2,%3};\n"
        : "+f"(d[0]), "+f"(d[1]), "+f"(d[2]), "+f"(d[3])
        : "r"(a4[0]), "r"(a4[1]), "r"(a4[2]), "r"(a4[3]), "r"(b2[0]), "r"(b2[1]));
}

// ---------------- block reductions (fixed order) ------------------------------
__device__ __forceinline__ float blockReduceSum(float v, float* red) {
    #pragma unroll
    for (int o = 16; o; o >>= 1) v += __shfl_xor_sync(0xffffffffu, v, o);
    if ((threadIdx.x & 31) == 0) red[threadIdx.x >> 5] = v;
    __syncthreads();
    float t = 0.f;
    int nw = blockDim.x >> 5;
    for (int i = 0; i < nw; i++) t += red[i];
    __syncthreads();
    return t;
}
__device__ __forceinline__ float blockReduceMax(float v, float* red) {
    #pragma unroll
    for (int o = 16; o; o >>= 1) v = fmaxf(v, __shfl_xor_sync(0xffffffffu, v, o));
    if ((threadIdx.x & 31) == 0) red[threadIdx.x >> 5] = v;
    __syncthreads();
    float t = red[0];
    int nw = blockDim.x >> 5;
    for (int i = 1; i < nw; i++) t = fmaxf(t, red[i]);
    __syncthreads();
    return t;
}

// ---------------- one-time prep kernels ---------------------------------------
__global__ void k_transpose(const float* __restrict__ in, float* __restrict__ out, int R, int Ccols) {
    __shared__ float t[32][33];
    int c0 = blockIdx.x * 32, r0 = blockIdx.y * 32;
    #pragma unroll
    for (int i = 0; i < 4; i++)
        t[threadIdx.y + i * 8][threadIdx.x] = in[(size_t)(r0 + threadIdx.y + i * 8) * Ccols + c0 + threadIdx.x];
    __syncthreads();
    #pragma unroll
    for (int i = 0; i < 4; i++)
        out[(size_t)(c0 + threadIdx.y + i * 8) * R + r0 + threadIdx.x] = t[threadIdx.x][threadIdx.y + i * 8];
}
__global__ void k_cvt_bf16(const float* __restrict__ in, __nv_bfloat16* __restrict__ out) {
    size_t i = ((size_t)blockIdx.x * 256 + threadIdx.x) * 4;
    float4 v = *(const float4*)&in[i];
    __nv_bfloat162* o = (__nv_bfloat162*)&out[i];
    o[0] = __floats2bfloat162_rn(v.x, v.y);
    o[1] = __floats2bfloat162_rn(v.z, v.w);
}
__global__ void k_zero_h() { g_h[blockIdx.x * 256 + threadIdx.x] = 0.f; }

// ============ TF32 NT GEMM, M=128 tile (ctx_proj): C[M,N]=A[M,K]@B[N,K]^T =====
__global__ __launch_bounds__(256) void gemm_tf32_m128(
    const float* __restrict__ A, const float* __restrict__ B,
    float* __restrict__ C, int N, int K) {
    __shared__ float As[128][36];
    __shared__ float Bs[128][36];
    const int row0 = blockIdx.y * 128, col0 = blockIdx.x * 128;
    const int tid = threadIdx.x;
    const int wid = tid >> 5, lane = tid & 31;
    const int gID = lane >> 2, tig = lane & 3;
    const int m0w = (wid >> 2) * 64, n0w = (wid & 3) * 32;
    const int lrow = tid >> 1, lseg = (tid & 1) * 16;
    float acc[4][4][4] = {};
    for (int k0 = 0; k0 < K; k0 += 32) {
        #pragma unroll
        for (int i = 0; i < 4; i++) {
            float4 a = *(const float4*)&A[(size_t)(row0 + lrow) * K + k0 + lseg + i * 4];
            a.x = to_tf32(a.x); a.y = to_tf32(a.y); a.z = to_tf32(a.z); a.w = to_tf32(a.w);
            *(float4*)&As[lrow][lseg + i * 4] = a;
            float4 b = *(const float4*)&B[(size_t)(col0 + lrow) * K + k0 + lseg + i * 4];
            b.x = to_tf32(b.x); b.y = to_tf32(b.y); b.z = to_tf32(b.z); b.w = to_tf32(b.w);
            *(float4*)&Bs[lrow][lseg + i * 4] = b;
        }
        __syncthreads();
        #pragma unroll
        for (int kk = 0; kk < 4; kk++) {
            const int kb = kk * 8;
            float af[4][4], bf[4][2];
            #pragma unroll
            for (int mi = 0; mi < 4; mi++) {
                int r = m0w + mi * 16 + gID;
                af[mi][0] = As[r][kb + tig];     af[mi][1] = As[r + 8][kb + tig];
                af[mi][2] = As[r][kb + tig + 4]; af[mi][3] = As[r + 8][kb + tig + 4];
            }
            #pragma unroll
            for (int ni = 0; ni < 4; ni++) {
                int n = n0w + ni * 8 + gID;
                bf[ni][0] = Bs[n][kb + tig]; bf[ni][1] = Bs[n][kb + tig + 4];
            }
            #pragma unroll
            for (int mi = 0; mi < 4; mi++)
                #pragma unroll
                for (int ni = 0; ni < 4; ni++)
                    mma_tf32(acc[mi][ni], af[mi], bf[ni]);
        }
        __syncthreads();
    }
    #pragma unroll
    for (int mi = 0; mi < 4; mi++)
        #pragma unroll
        for (int ni = 0; ni < 4; ni++) {
            int r = row0 + m0w + mi * 16 + gID;
            int c = col0 + n0w + ni * 8 + tig * 2;
            *(float2*)&C[(size_t)r * N + c]       = make_float2(acc[mi][ni][0], acc[mi][ni][1]);
            *(float2*)&C[(size_t)(r + 8) * N + c] = make_float2(acc[mi][ni][2], acc[mi][ni][3]);
        }
}

// ============ TF32 NT GEMM, M=64, Ntile=64 (dual-problem capable) =============
__global__ __launch_bounds__(256) void gemm_tf32_m64(
    const float* __restrict__ A0, const float* __restrict__ B0, float* __restrict__ C0,
    const float* __restrict__ A1, const float* __restrict__ B1, float* __restrict__ C1,
    int N, int K) {
    const float* A = A0; const float* B = B0; float* C = C0;
    if (blockIdx.y == 1) { A = A1; B = B1; C = C1; }
    __shared__ float As[64][36];
    __shared__ float Bs[64][36];
    const int col0 = blockIdx.x * 64;
    const int tid = threadIdx.x;
    const int wid = tid >> 5, lane = tid & 31;
    const int gID = lane >> 2, tig = lane & 3;
    const int lrow = tid >> 2, lseg = (tid & 3) * 8;
    float acc[4][4] = {};
    for (int k0 = 0; k0 < K; k0 += 32) {
        #pragma unroll
        for (int i = 0; i < 2; i++) {
            float4 a = *(const float4*)&A[(size_t)lrow * K + k0 + lseg + i * 4];
            a.x = to_tf32(a.x); a.y = to_tf32(a.y); a.z = to_tf32(a.z); a.w = to_tf32(a.w);
            *(float4*)&As[lrow][lseg + i * 4] = a;
            float4 b = *(const float4*)&B[(size_t)(col0 + lrow) * K + k0 + lseg + i * 4];
            b.x = to_tf32(b.x); b.y = to_tf32(b.y); b.z = to_tf32(b.z); b.w = to_tf32(b.w);
            *(float4*)&Bs[lrow][lseg + i * 4] = b;
        }
        __syncthreads();
        #pragma unroll
        for (int kk = 0; kk < 4; kk++) {
            const int kb = kk * 8;
            float bf[2];
            bf[0] = Bs[wid * 8 + gID][kb + tig]; bf[1] = Bs[wid * 8 + gID][kb + tig + 4];
            #pragma unroll
            for (int mi = 0; mi < 4; mi++) {
                float af[4];
                int r = mi * 16 + gID;
                af[0] = As[r][kb + tig];     af[1] = As[r + 8][kb + tig];
                af[2] = As[r][kb + tig + 4]; af[3] = As[r + 8][kb + tig + 4];
                mma_tf32(acc[mi], af, bf);
            }
        }
        __syncthreads();
    }
    #pragma unroll
    for (int mi = 0; mi < 4; mi++) {
        int r = mi * 16 + gID;
        int c = col0 + wid * 8 + tig * 2;
        *(float2*)&C[(size_t)r * N + c]       = make_float2(acc[mi][0], acc[mi][1]);
        *(float2*)&C[(size_t)(r + 8) * N + c] = make_float2(acc[mi][2], acc[mi][3]);
    }
}

// ============ TF32 NT GEMM for gi: A gathered as [emb(y[t]) | z] ==============
__global__ __launch_bounds__(256) void gemm_tf32_gi(
    const float* __restrict__ embW, const int* __restrict__ y, int t,
    const float* __restrict__ B, float* __restrict__ C, int N, int K) {
    __shared__ float As[64][36];
    __shared__ float Bs[64][36];
    const int col0 = blockIdx.x * 64;
    const int tid = threadIdx.x;
    const int wid = tid >> 5, lane = tid & 31;
    const int gID = lane >> 2, tig = lane & 3;
    const int lrow = tid >> 2, lseg = (tid & 3) * 8;
    const int yid = y[t * Bn + lrow];
    float acc[4][4] = {};
    for (int k0 = 0; k0 < K; k0 += 32) {
        const float* Arow = (k0 < Edim)
            ? &embW[(size_t)yid * Edim + k0]
            : &g_z[lrow * Cdim + (k0 - Edim)];
        #pragma unroll
        for (int i = 0; i < 2; i++) {
            float4 a = *(const float4*)&Arow[lseg + i * 4];
            a.x = to_tf32(a.x); a.y = to_tf32(a.y); a.z = to_tf32(a.z); a.w = to_tf32(a.w);
            *(float4*)&As[lrow][lseg + i * 4] = a;
            float4 b = *(const float4*)&B[(size_t)(col0 + lrow) * K + k0 + lseg + i * 4];
            b.x = to_tf32(b.x); b.y = to_tf32(b.y); b.z = to_tf32(b.z); b.w = to_tf32(b.w);
            *(float4*)&Bs[lrow][lseg + i * 4] = b;
        }
        __syncthreads();
        #pragma unroll
        for (int kk = 0; kk < 4; kk++) {
            const int kb = kk * 8;
            float bf[2];
            bf[0] = Bs[wid * 8 + gID][kb + tig]; bf[1] = Bs[wid * 8 + gID][kb + tig + 4];
            #pragma unroll
            for (int mi = 0; mi < 4; mi++) {
                float af[4];
                int r = mi * 16 + gID;
                af[0] = As[r][kb + tig];     af[1] = As[r + 8][kb + tig];
                af[2] = As[r][kb + tig + 4]; af[3] = As[r + 8][kb + tig + 4];
                mma_tf32(acc[mi], af, bf);
            }
        }
        __syncthreads();
    }
    #pragma unroll
    for (int mi = 0; mi < 4; mi++) {
        int r = mi * 16 + gID;
        int c = col0 + wid * 8 + tig * 2;
        *(float2*)&C[(size_t)r * N + c]       = make_float2(acc[mi][0], acc[mi][1]);
        *(float2*)&C[(size_t)(r + 8) * N + c] = make_float2(acc[mi][2], acc[mi][3]);
    }
}

// ============ BF16 NT GEMM, M=64, Ntile=256 (logits) ==========================
__global__ __launch_bounds__(256) void gemm_bf16_logits(
    const __nv_bfloat16* __restrict__ A, const __nv_bfloat16* __restrict__ B,
    float* __restrict__ C, int N, int K) {
    __shared__ __nv_bfloat16 As[64][72];
    __shared__ __nv_bfloat16 Bs[256][72];
    const int col0 = blockIdx.x * 256;
    const int tid = threadIdx.x;
    const int wid = tid >> 5, lane = tid & 31;
    const int gID = lane >> 2, tig = lane & 3;
    const int n0w = wid * 32;
    float acc[4][4][4] = {};
    for (int k0 = 0; k0 < K; k0 += 64) {
        {
            int ar = tid >> 2, as = (tid & 3) * 16;
            *(uint4*)&As[ar][as]     = *(const uint4*)&A[(size_t)ar * K + k0 + as];
            *(uint4*)&As[ar][as + 8] = *(const uint4*)&A[(size_t)ar * K + k0 + as + 8];
            #pragma unroll
            for (int i = 0; i < 8; i++)
                *(uint4*)&Bs[tid][i * 8] = *(const uint4*)&B[(size_t)(col0 + tid) * K + k0 + i * 8];
        }
        __syncthreads();
        #pragma unroll
        for (int kk = 0; kk < 4; kk++) {
            const int kb = kk * 16;
            unsigned af[4][4], bf[4][2];
            #pragma unroll
            for (int mi = 0; mi < 4; mi++) {
                int r = mi * 16 + gID;
                int c = kb + tig * 2;
                af[mi][0] = *(const unsigned*)&As[r][c];
                af[mi][1] = *(const unsigned*)&As[r + 8][c];
                af[mi][2] = *(const unsigned*)&As[r][c + 8];
                af[mi][3] = *(const unsigned*)&As[r + 8][c + 8];
            }
            #pragma unroll
            for (int ni = 0; ni < 4; ni++) {
                int n = n0w + ni * 8 + gID;
                int c = kb + tig * 2;
                bf[ni][0] = *(const unsigned*)&Bs[n][c];
                bf[ni][1] = *(const unsigned*)&Bs[n][c + 8];
            }
            #pragma unroll
            for (int mi = 0; mi < 4; mi++)
                #pragma unroll
                for (int ni = 0; ni < 4; ni++)
                    mma_bf16(acc[mi][ni], af[mi], bf[ni]);
        }
        __syncthreads();
    }
    #pragma unroll
    for (int mi = 0; mi < 4; mi++)
        #pragma unroll
        for (int ni = 0; ni < 4; ni++) {
            int r = mi * 16 + gID;
            int c = col0 + n0w + ni * 8 + tig * 2;
            *(float2*)&C[(size_t)r * N + c]       = make_float2(acc[mi][ni][0], acc[mi][ni][1]);
            *(float2*)&C[(size_t)(r + 8) * N + c] = make_float2(acc[mi][ni][2], acc[mi][ni][3]);
        }
}

// ---------------- per-step elementwise kernels --------------------------------
__global__ __launch_bounds__(256) void k_scores(const float* __restrict__ mlp) {
    const int sb = blockIdx.x;
    const int b = sb & (Bn - 1);
    const float* __restrict__ row = g_ctx_proj + (size_t)sb * Cdim;
    const float* __restrict__ hqr = g_hq + b * Cdim;
    __shared__ float red[8];
    const int m4 = threadIdx.x * 4;
    float4 r = *(const float4*)&row[m4];
    float4 h = *(const float4*)&hqr[m4];
    float4 w = *(const float4*)&mlp[m4];
    float sum = ftanh(r.x + h.x) * w.x + ftanh(r.y + h.y) * w.y
              + ftanh(r.z + h.z) * w.z + ftanh(r.w + h.w) * w.w;
    float tot = blockReduceSum(sum, red);
    if (threadIdx.x == 0) g_scores[sb] = tot;
}

// softmax over S (per b) + z[b,:] = sum_s alpha * ctx[s,b,:], fused
__global__ __launch_bounds__(256) void k_softz(const float* __restrict__ ctx) {
    const int b = blockIdx.x;
    __shared__ float red[8];
    __shared__ float al[Sdim];
    float v = (threadIdx.x < Sdim) ? g_scores[threadIdx.x * Bn + b] : -1e30f;
    float mx = blockReduceMax(v, red);
    float e = (threadIdx.x < Sdim) ? __expf(v - mx) : 0.f;
    float tot = blockReduceSum(e, red);
    if (threadIdx.x < Sdim) al[threadIdx.x] = __fdividef(e, tot);
    __syncthreads();
    const int c4 = threadIdx.x * 4;
    float4 sum = make_float4(0.f, 0.f, 0.f, 0.f);
    #pragma unroll 4
    for (int s = 0; s < Sdim; s++) {
        float a = al[s];
        float4 x = *(const float4*)&ctx[((size_t)s * Bn + b) * Cdim + c4];
        sum.x = fmaf(a, x.x, sum.x); sum.y = fmaf(a, x.y, sum.y);
        sum.z = fmaf(a, x.z, sum.z); sum.w = fmaf(a, x.w, sum.w);
    }
    *(float4*)&g_z[b * Cdim + c4] = sum;
}

__global__ void k_gru(const float* __restrict__ b_ih, const float* __restrict__ b_hh) {
    const int i = blockIdx.x * 256 + threadIdx.x;
    const int b = i >> 10, j = i & (Hdim - 1);
    const float* gi = g_gi + b * 3 * Hdim;
    const float* gh = g_gh + b * 3 * Hdim;
    float ir = gi[j] + b_ih[j];
    float iz = gi[Hdim + j] + b_ih[Hdim + j];
    float in_ = gi[2 * Hdim + j] + b_ih[2 * Hdim + j];
    float hr = gh[j] + b_hh[j];
    float hz = gh[Hdim + j] + b_hh[Hdim + j];
    float hn = gh[2 * Hdim + j] + b_hh[2 * Hdim + j];
    float r = fsig(ir + hr);
    float zz = fsig(iz + hz);
    float n = ftanh(in_ + r * hn);
    float hold = g_h[i];
    g_h[i] = (1.f - zz) * n + zz * hold;
}

__global__ void k_pvec(const float* __restrict__ embW, const int* __restrict__ y,
                       const float* __restrict__ h2o_b, const float* __restrict__ octx_b, int t) {
    const int i = blockIdx.x * 256 + threadIdx.x;
    const int b = i >> 9, e = i & (Edim - 1);
    float l = ftanh(g_o1[i] + h2o_b[e]);
    l += embW[(size_t)y[t * Bn + b] * Edim + e];
    l += g_o2[i] + octx_b[e];
    g_p_bf16[i] = __float2bfloat16_rn(ftanh(l));
}

__global__ __launch_bounds__(512) void k_nll(const int* __restrict__ y,
                                             const float* __restrict__ bias, int t) {
    const int b = blockIdx.x;
    const float* __restrict__ row = g_logits + (size_t)b * Vdim;
    __shared__ float red[16];
    float m = -1e30f;
    for (int v = threadIdx.x; v < Vdim; v += 512) m = fmaxf(m, row[v] + bias[v]);
    float mx = blockReduceMax(m, red);
    float s = 0.f;
    for (int v = threadIdx.x; v < Vdim; v += 512) s += __expf(row[v] + bias[v] - mx);
    float tot = blockReduceSum(s, red);
    if (threadIdx.x == 0) {
        int tgt = y[(t + 1) * Bn + b];
        float lse = mx + logf(tot);
        g_nll[t * Bn + b] = (tgt != 0) ? (lse - (row[tgt] + bias[tgt])) : 0.f;
    }
}

__global__ void k_final(float* __restrict__ out) {
    __shared__ float red[8];
    float s = 0.f;
    for (int i = threadIdx.x; i < NSTEP * Bn; i += 256) s += g_nll[i];
    float tot = blockReduceSum(s, red);
    if (threadIdx.x == 0) out[0] = tot;
}

// ---------------- launch ------------------------------------------------------
extern "C" void kernel_launch(void* const* d_in, const int* in_sizes, int n_in,
                              void* d_out, int out_size) {
    const float* ctx         = (const float*)d_in[0];
    const int*   y           = (const int*)  d_in[1];
    const float* embW        = (const float*)d_in[2];
    const float* att_ctx2ctx = (const float*)d_in[3];
    const float* att_hid2ctx = (const float*)d_in[4];
    const float* att_mlp     = (const float*)d_in[5];
    const float* gru_W_ih    = (const float*)d_in[6];
    const float* gru_b_ih    = (const float*)d_in[7];
    const float* gru_W_hh    = (const float*)d_in[8];
    const float* gru_b_hh    = (const float*)d_in[9];
    const float* h2o_W       = (const float*)d_in[10];
    const float* h2o_b       = (const float*)d_in[11];
    const float* octx_W      = (const float*)d_in[12];
    const float* octx_b      = (const float*)d_in[13];
    const float* o2p_W       = (const float*)d_in[14];
    const float* o2p_b       = (const float*)d_in[15];

    float *p_ctxproj, *p_WctxT, *p_WhidT, *p_h, *p_hq, *p_z, *p_gi, *p_gh, *p_o1, *p_o2, *p_logits;
    __nv_bfloat16 *p_Wbf, *p_pbf;
    cudaGetSymbolAddress((void**)&p_ctxproj, g_ctx_proj);
    cudaGetSymbolAddress((void**)&p_WctxT,   g_WctxT);
    cudaGetSymbolAddress((void**)&p_WhidT,   g_WhidT);
    cudaGetSymbolAddress((void**)&p_Wbf,     g_Wo2p_bf16);
    cudaGetSymbolAddress((void**)&p_pbf,     g_p_bf16);
    cudaGetSymbolAddress((void**)&p_h,       g_h);
    cudaGetSymbolAddress((void**)&p_hq,      g_hq);
    cudaGetSymbolAddress((void**)&p_z,       g_z);
    cudaGetSymbolAddress((void**)&p_gi,      g_gi);
    cudaGetSymbolAddress((void**)&p_gh,      g_gh);
    cudaGetSymbolAddress((void**)&p_o1,      g_o1);
    cudaGetSymbolAddress((void**)&p_o2,      g_o2);
    cudaGetSymbolAddress((void**)&p_logits,  g_logits);

    // one-time prep
    k_transpose<<<dim3(32, 32), dim3(32, 8)>>>(att_ctx2ctx, p_WctxT, Cdim, Cdim);
    k_transpose<<<dim3(32, 32), dim3(32, 8)>>>(att_hid2ctx, p_WhidT, Hdim, Cdim);
    k_cvt_bf16<<<((size_t)Vdim * Edim) / 1024, 256>>>(o2p_W, p_Wbf);
    k_zero_h<<<(Bn * Hdim) / 256, 256>>>();

    // ctx_proj = ctx @ att_ctx2ctx  (tf32 NT vs transposed weight)
    gemm_tf32_m128<<<dim3(Cdim / 128, (Sdim * Bn) / 128), 256>>>(
        ctx, p_WctxT, p_ctxproj, Cdim, Cdim);

    for (int t = 0; t < NSTEP; t++) {
        gemm_tf32_m64<<<dim3(Cdim / 64, 1), 256>>>(
            p_h, p_WhidT, p_hq, p_h, p_WhidT, p_hq, Cdim, Hdim);
        k_scores<<<Sdim * Bn, 256>>>(att_mlp);
        k_softz<<<Bn, 256>>>(ctx);
        gemm_tf32_gi<<<dim3((3 * Hdim) / 64, 1), 256>>>(
            embW, y, t, gru_W_ih, p_gi, 3 * Hdim, Edim + Cdim);
        gemm_tf32_m64<<<dim3((3 * Hdim) / 64, 1), 256>>>(
            p_h, gru_W_hh, p_gh, p_h, gru_W_hh, p_gh, 3 * Hdim, Hdim);
        k_gru<<<(Bn * Hdim) / 256, 256>>>(gru_b_ih, gru_b_hh);
        gemm_tf32_m64<<<dim3(Edim / 64, 2), 256>>>(
            p_h, h2o_W, p_o1, p_z, octx_W, p_o2, Edim, Hdim);
        k_pvec<<<(Bn * Edim) / 256, 256>>>(embW, y, h2o_b, octx_b, t);
        gemm_bf16_logits<<<Vdim / 256, 256>>>(p_pbf, p_Wbf, p_logits, Vdim, Edim);
        k_nll<<<Bn, 512>>>(y, o2p_b, t);
    }
    k_final<<<1, 256>>>((float*)d_out);
}

// round 6
// speedup vs baseline: 2.9891x; 1.4625x over previous
#include <cuda_runtime.h>
#include <cuda_bf16.h>
#include <math.h>

#define Sdim 196
#define Bn   64
#define Cdim 1024
#define Hdim 1024
#define Edim 512
#define Vdim 32000
#define NSTEP 19

// ---------------- scratch (device globals) -----------------------------------
__device__ __nv_bfloat16 g_ctxp_bf16[(size_t)Sdim * Bn * Cdim];  // ctx_proj bf16
__device__ __nv_bfloat16 g_ctx_bf16[(size_t)Sdim * Bn * Cdim];   // ctx bf16 copy
__device__ float g_WctxT[Cdim * Cdim];
__device__ float g_WhidT[Hdim * Cdim];
__device__ __nv_bfloat16 g_Wo2p_bf16[(size_t)Vdim * Edim];
__device__ __nv_bfloat16 g_p_bf16[Bn * Edim];
__device__ float g_h[Bn * Hdim];
__device__ float g_hq_part[4 * Bn * Cdim];
__device__ float g_z[Bn * Cdim];
__device__ float g_gi_part[4 * Bn * 3 * Hdim];
__device__ float g_gh_part[4 * Bn * 3 * Hdim];
__device__ float g_o1_part[4 * Bn * Edim];
__device__ float g_o2_part[4 * Bn * Edim];
__device__ float g_logits[(size_t)Bn * Vdim];
__device__ float g_nll[NSTEP * Bn];

// ---------------- fast math ---------------------------------------------------
__device__ __forceinline__ float ftanh(float x) {
    float xc = fminf(fmaxf(x, -15.f), 15.f);
    float e = __expf(2.f * xc);
    return __fdividef(e - 1.f, e + 1.f);
}
__device__ __forceinline__ float ftanh_fast(float x) {
    float y;
    asm("tanh.approx.f32 %0, %1;" : "=f"(y) : "f"(x));
    return y;
}
__device__ __forceinline__ float fsig(float x) {
    return __fdividef(1.f, 1.f + __expf(-x));
}
__device__ __forceinline__ float to_tf32(float x) {
    unsigned u;
    asm("cvt.rna.tf32.f32 %0, %1;" : "=r"(u) : "f"(x));
    return __uint_as_float(u);
}
__device__ __forceinline__ void mma_tf32(float* d, const float* a4, const float* b2) {
    asm volatile(
        "mma.sync.aligned.m16n8k8.row.col.f32.tf32.tf32.f32 "
        "{%0,%1,%2,%3}, {%4,%5,%6,%7}, {%8,%9}, {%0,%1,%2,%3};\n"
        : "+f"(d[0]), "+f"(d[1]), "+f"(d[2]), "+f"(d[3])
        : "r"(__float_as_uint(a4[0])), "r"(__float_as_uint(a4[1])),
          "r"(__float_as_uint(a4[2])), "r"(__float_as_uint(a4[3])),
          "r"(__float_as_uint(b2[0])), "r"(__float_as_uint(b2[1])));
}
__device__ __forceinline__ void mma_bf16(float* d, const unsigned* a4, const unsigned* b2) {
    asm volatile(
        "mma.sync.aligned.m16n8k16.row.col.f32.bf16.bf16.f32 "
        "{%0,%1,%2,%3}, {%4,%5,%6,%7}, {%8,%9}, {%0,%1,%2,%3};\n"
        : "+f"(d[0]), "+f"(d[1]), "+f"(d[2]), "+f"(d[3])
        : "r"(a4[0]), "r"(a4[1]), "r"(a4[2]), "r"(a4[3]), "r"(b2[0]), "r"(b2[1]));
}

// ---------------- block reductions (fixed order) ------------------------------
__device__ __forceinline__ float blockReduceSum(float v, float* red) {
    #pragma unroll
    for (int o = 16; o; o >>= 1) v += __shfl_xor_sync(0xffffffffu, v, o);
    if ((threadIdx.x & 31) == 0) red[threadIdx.x >> 5] = v;
    __syncthreads();
    float t = 0.f;
    int nw = blockDim.x >> 5;
    for (int i = 0; i < nw; i++) t += red[i];
    __syncthreads();
    return t;
}
__device__ __forceinline__ float blockReduceMax(float v, float* red) {
    #pragma unroll
    for (int o = 16; o; o >>= 1) v = fmaxf(v, __shfl_xor_sync(0xffffffffu, v, o));
    if ((threadIdx.x & 31) == 0) red[threadIdx.x >> 5] = v;
    __syncthreads();
    float t = red[0];
    int nw = blockDim.x >> 5;
    for (int i = 1; i < nw; i++) t = fmaxf(t, red[i]);
    __syncthreads();
    return t;
}

// ---------------- one-time prep kernels ---------------------------------------
__global__ void k_transpose(const float* __restrict__ in, float* __restrict__ out, int R, int Ccols) {
    __shared__ float t[32][33];
    int c0 = blockIdx.x * 32, r0 = blockIdx.y * 32;
    #pragma unroll
    for (int i = 0; i < 4; i++)
        t[threadIdx.y + i * 8][threadIdx.x] = in[(size_t)(r0 + threadIdx.y + i * 8) * Ccols + c0 + threadIdx.x];
    __syncthreads();
    #pragma unroll
    for (int i = 0; i < 4; i++)
        out[(size_t)(c0 + threadIdx.y + i * 8) * R + r0 + threadIdx.x] = t[threadIdx.x][threadIdx.y + i * 8];
}
__global__ void k_cvt_bf16(const float* __restrict__ in, __nv_bfloat16* __restrict__ out) {
    size_t i = ((size_t)blockIdx.x * 256 + threadIdx.x) * 4;
    float4 v = *(const float4*)&in[i];
    __nv_bfloat162* o = (__nv_bfloat162*)&out[i];
    o[0] = __floats2bfloat162_rn(v.x, v.y);
    o[1] = __floats2bfloat162_rn(v.z, v.w);
}
__global__ void k_zero_h() { g_h[blockIdx.x * 256 + threadIdx.x] = 0.f; }

// ============ TF32 NT GEMM, M=128 tile -> bf16 out (ctx_proj) =================
__global__ __launch_bounds__(256) void gemm_tf32_m128_bf16out(
    const float* __restrict__ A, const float* __restrict__ B,
    __nv_bfloat16* __restrict__ C, int N, int K) {
    __shared__ float As[128][36];
    __shared__ float Bs[128][36];
    const int row0 = blockIdx.y * 128, col0 = blockIdx.x * 128;
    const int tid = threadIdx.x;
    const int wid = tid >> 5, lane = tid & 31;
    const int gID = lane >> 2, tig = lane & 3;
    const int m0w = (wid >> 2) * 64, n0w = (wid & 3) * 32;
    const int lrow = tid >> 1, lseg = (tid & 1) * 16;
    float acc[4][4][4] = {};
    for (int k0 = 0; k0 < K; k0 += 32) {
        #pragma unroll
        for (int i = 0; i < 4; i++) {
            float4 a = *(const float4*)&A[(size_t)(row0 + lrow) * K + k0 + lseg + i * 4];
            a.x = to_tf32(a.x); a.y = to_tf32(a.y); a.z = to_tf32(a.z); a.w = to_tf32(a.w);
            *(float4*)&As[lrow][lseg + i * 4] = a;
            float4 b = *(const float4*)&B[(size_t)(col0 + lrow) * K + k0 + lseg + i * 4];
            b.x = to_tf32(b.x); b.y = to_tf32(b.y); b.z = to_tf32(b.z); b.w = to_tf32(b.w);
            *(float4*)&Bs[lrow][lseg + i * 4] = b;
        }
        __syncthreads();
        #pragma unroll
        for (int kk = 0; kk < 4; kk++) {
            const int kb = kk * 8;
            float af[4][4], bf[4][2];
            #pragma unroll
            for (int mi = 0; mi < 4; mi++) {
                int r = m0w + mi * 16 + gID;
                af[mi][0] = As[r][kb + tig];     af[mi][1] = As[r + 8][kb + tig];
                af[mi][2] = As[r][kb + tig + 4]; af[mi][3] = As[r + 8][kb + tig + 4];
            }
            #pragma unroll
            for (int ni = 0; ni < 4; ni++) {
                int n = n0w + ni * 8 + gID;
                bf[ni][0] = Bs[n][kb + tig]; bf[ni][1] = Bs[n][kb + tig + 4];
            }
            #pragma unroll
            for (int mi = 0; mi < 4; mi++)
                #pragma unroll
                for (int ni = 0; ni < 4; ni++)
                    mma_tf32(acc[mi][ni], af[mi], bf[ni]);
        }
        __syncthreads();
    }
    #pragma unroll
    for (int mi = 0; mi < 4; mi++)
        #pragma unroll
        for (int ni = 0; ni < 4; ni++) {
            int r = row0 + m0w + mi * 16 + gID;
            int c = col0 + n0w + ni * 8 + tig * 2;
            *(__nv_bfloat162*)&C[(size_t)r * N + c]       = __floats2bfloat162_rn(acc[mi][ni][0], acc[mi][ni][1]);
            *(__nv_bfloat162*)&C[(size_t)(r + 8) * N + c] = __floats2bfloat162_rn(acc[mi][ni][2], acc[mi][ni][3]);
        }
}

// ============ TF32 NT GEMM, M=64, split-K, dual problem =======================
// Partial C written at C + blockIdx.z*64*N.
__global__ __launch_bounds__(256) void gemm_tf32_m64_sk(
    const float* __restrict__ A0, const float* __restrict__ B0, float* __restrict__ C0,
    const float* __restrict__ A1, const float* __restrict__ B1, float* __restrict__ C1,
    int N, int K, int kChunk) {
    const float* A = A0; const float* B = B0; float* C = C0;
    if (blockIdx.y == 1) { A = A1; B = B1; C = C1; }
    __shared__ float As[64][36];
    __shared__ float Bs[64][36];
    const int col0 = blockIdx.x * 64;
    const int kbase = blockIdx.z * kChunk;
    const int tid = threadIdx.x;
    const int wid = tid >> 5, lane = tid & 31;
    const int gID = lane >> 2, tig = lane & 3;
    const int lrow = tid >> 2, lseg = (tid & 3) * 8;
    float acc[4][4] = {};
    for (int kt = 0; kt < kChunk; kt += 32) {
        const int k0 = kbase + kt;
        #pragma unroll
        for (int i = 0; i < 2; i++) {
            float4 a = *(const float4*)&A[(size_t)lrow * K + k0 + lseg + i * 4];
            a.x = to_tf32(a.x); a.y = to_tf32(a.y); a.z = to_tf32(a.z); a.w = to_tf32(a.w);
            *(float4*)&As[lrow][lseg + i * 4] = a;
            float4 b = *(const float4*)&B[(size_t)(col0 + lrow) * K + k0 + lseg + i * 4];
            b.x = to_tf32(b.x); b.y = to_tf32(b.y); b.z = to_tf32(b.z); b.w = to_tf32(b.w);
            *(float4*)&Bs[lrow][lseg + i * 4] = b;
        }
        __syncthreads();
        #pragma unroll
        for (int kk = 0; kk < 4; kk++) {
            const int kb = kk * 8;
            float bfv[2];
            bfv[0] = Bs[wid * 8 + gID][kb + tig]; bfv[1] = Bs[wid * 8 + gID][kb + tig + 4];
            #pragma unroll
            for (int mi = 0; mi < 4; mi++) {
                float af[4];
                int r = mi * 16 + gID;
                af[0] = As[r][kb + tig];     af[1] = As[r + 8][kb + tig];
                af[2] = As[r][kb + tig + 4]; af[3] = As[r + 8][kb + tig + 4];
                mma_tf32(acc[mi], af, bfv);
            }
        }
        __syncthreads();
    }
    float* Cp = C + (size_t)blockIdx.z * 64 * N;
    #pragma unroll
    for (int mi = 0; mi < 4; mi++) {
        int r = mi * 16 + gID;
        int c = col0 + wid * 8 + tig * 2;
        *(float2*)&Cp[(size_t)r * N + c]       = make_float2(acc[mi][0], acc[mi][1]);
        *(float2*)&Cp[(size_t)(r + 8) * N + c] = make_float2(acc[mi][2], acc[mi][3]);
    }
}

// ============ TF32 NT GEMM for gi, split-K, A gathered [emb(y)|z] =============
__global__ __launch_bounds__(256) void gemm_tf32_gi_sk(
    const float* __restrict__ embW, const int* __restrict__ y, int t,
    const float* __restrict__ B, float* __restrict__ C, int N, int K, int kChunk) {
    __shared__ float As[64][36];
    __shared__ float Bs[64][36];
    const int col0 = blockIdx.x * 64;
    const int kbase = blockIdx.z * kChunk;
    const int tid = threadIdx.x;
    const int wid = tid >> 5, lane = tid & 31;
    const int gID = lane >> 2, tig = lane & 3;
    const int lrow = tid >> 2, lseg = (tid & 3) * 8;
    const int yid = y[t * Bn + lrow];
    float acc[4][4] = {};
    for (int kt = 0; kt < kChunk; kt += 32) {
        const int k0 = kbase + kt;
        const float* Arow = (k0 < Edim)
            ? &embW[(size_t)yid * Edim + k0]
            : &g_z[lrow * Cdim + (k0 - Edim)];
        #pragma unroll
        for (int i = 0; i < 2; i++) {
            float4 a = *(const float4*)&Arow[lseg + i * 4];
            a.x = to_tf32(a.x); a.y = to_tf32(a.y); a.z = to_tf32(a.z); a.w = to_tf32(a.w);
            *(float4*)&As[lrow][lseg + i * 4] = a;
            float4 b = *(const float4*)&B[(size_t)(col0 + lrow) * K + k0 + lseg + i * 4];
            b.x = to_tf32(b.x); b.y = to_tf32(b.y); b.z = to_tf32(b.z); b.w = to_tf32(b.w);
            *(float4*)&Bs[lrow][lseg + i * 4] = b;
        }
        __syncthreads();
        #pragma unroll
        for (int kk = 0; kk < 4; kk++) {
            const int kb = kk * 8;
            float bfv[2];
            bfv[0] = Bs[wid * 8 + gID][kb + tig]; bfv[1] = Bs[wid * 8 + gID][kb + tig + 4];
            #pragma unroll
            for (int mi = 0; mi < 4; mi++) {
                float af[4];
                int r = mi * 16 + gID;
                af[0] = As[r][kb + tig];     af[1] = As[r + 8][kb + tig];
                af[2] = As[r][kb + tig + 4]; af[3] = As[r + 8][kb + tig + 4];
                mma_tf32(acc[mi], af, bfv);
            }
        }
        __syncthreads();
    }
    float* Cp = C + (size_t)blockIdx.z * 64 * N;
    #pragma unroll
    for (int mi = 0; mi < 4; mi++) {
        int r = mi * 16 + gID;
        int c = col0 + wid * 8 + tig * 2;
        *(float2*)&Cp[(size_t)r * N + c]       = make_float2(acc[mi][0], acc[mi][1]);
        *(float2*)&Cp[(size_t)(r + 8) * N + c] = make_float2(acc[mi][2], acc[mi][3]);
    }
}

// ============ BF16 NT GEMM, M=64, Ntile=256 (logits) ==========================
__global__ __launch_bounds__(256) void gemm_bf16_logits(
    const __nv_bfloat16* __restrict__ A, const __nv_bfloat16* __restrict__ B,
    float* __restrict__ C, int N, int K) {
    __shared__ __nv_bfloat16 As[64][72];
    __shared__ __nv_bfloat16 Bs[256][72];
    const int col0 = blockIdx.x * 256;
    const int tid = threadIdx.x;
    const int wid = tid >> 5, lane = tid & 31;
    const int gID = lane >> 2, tig = lane & 3;
    const int n0w = wid * 32;
    float acc[4][4][4] = {};
    for (int k0 = 0; k0 < K; k0 += 64) {
        {
            int ar = tid >> 2, as = (tid & 3) * 16;
            *(uint4*)&As[ar][as]     = *(const uint4*)&A[(size_t)ar * K + k0 + as];
            *(uint4*)&As[ar][as + 8] = *(const uint4*)&A[(size_t)ar * K + k0 + as + 8];
            #pragma unroll
            for (int i = 0; i < 8; i++)
                *(uint4*)&Bs[tid][i * 8] = *(const uint4*)&B[(size_t)(col0 + tid) * K + k0 + i * 8];
        }
        __syncthreads();
        #pragma unroll
        for (int kk = 0; kk < 4; kk++) {
            const int kb = kk * 16;
            unsigned af[4][4], bf[4][2];
            #pragma unroll
            for (int mi = 0; mi < 4; mi++) {
                int r = mi * 16 + gID;
                int c = kb + tig * 2;
                af[mi][0] = *(const unsigned*)&As[r][c];
                af[mi][1] = *(const unsigned*)&As[r + 8][c];
                af[mi][2] = *(const unsigned*)&As[r][c + 8];
                af[mi][3] = *(const unsigned*)&As[r + 8][c + 8];
            }
            #pragma unroll
            for (int ni = 0; ni < 4; ni++) {
                int n = n0w + ni * 8 + gID;
                int c = kb + tig * 2;
                bf[ni][0] = *(const unsigned*)&Bs[n][c];
                bf[ni][1] = *(const unsigned*)&Bs[n][c + 8];
            }
            #pragma unroll
            for (int mi = 0; mi < 4; mi++)
                #pragma unroll
                for (int ni = 0; ni < 4; ni++)
                    mma_bf16(acc[mi][ni], af[mi], bf[ni]);
        }
        __syncthreads();
    }
    #pragma unroll
    for (int mi = 0; mi < 4; mi++)
        #pragma unroll
        for (int ni = 0; ni < 4; ni++) {
            int r = mi * 16 + gID;
            int c = col0 + n0w + ni * 8 + tig * 2;
            *(float2*)&C[(size_t)r * N + c]       = make_float2(acc[mi][ni][0], acc[mi][ni][1]);
            *(float2*)&C[(size_t)(r + 8) * N + c] = make_float2(acc[mi][ni][2], acc[mi][ni][3]);
        }
}

// ============ fused attention: scores + softmax + z (one block per b) =========
__global__ __launch_bounds__(256) void k_att(const float* __restrict__ mlp) {
    const int b = blockIdx.x;
    const int tid = threadIdx.x;
    const int wid = tid >> 5, lane = tid & 31;
    __shared__ float sc[200];
    __shared__ float red[8];

    // hq[b,m] = sum of 4 split-K partials; keep this thread's 32 m-values in regs
    float hqv[32], mlpv[32];
    #pragma unroll
    for (int j = 0; j < 4; j++) {
        #pragma unroll
        for (int u = 0; u < 8; u++) {
            int m = lane * 8 + j * 256 + u;
            float v = g_hq_part[b * Cdim + m]
                    + g_hq_part[(Bn + b) * Cdim + m]
                    + g_hq_part[(2 * Bn + b) * Cdim + m]
                    + g_hq_part[(3 * Bn + b) * Cdim + m];
            hqv[j * 8 + u] = v;
            mlpv[j * 8 + u] = mlp[m];
        }
    }

    // Phase A: scores[s] = sum_m tanh(ctxp[s,b,m] + hq[m]) * mlp[m]
    for (int s = wid; s < Sdim; s += 8) {
        const __nv_bfloat16* row = g_ctxp_bf16 + ((size_t)s * Bn + b) * Cdim;
        float sum = 0.f;
        #pragma unroll
        for (int j = 0; j < 4; j++) {
            int m = lane * 8 + j * 256;
            uint4 u = *(const uint4*)&row[m];
            float2 f0 = __bfloat1622float2(*(__nv_bfloat162*)&u.x);
            float2 f1 = __bfloat1622float2(*(__nv_bfloat162*)&u.y);
            float2 f2 = __bfloat1622float2(*(__nv_bfloat162*)&u.z);
            float2 f3 = __bfloat1622float2(*(__nv_bfloat162*)&u.w);
            sum += ftanh_fast(f0.x + hqv[j * 8 + 0]) * mlpv[j * 8 + 0];
            sum += ftanh_fast(f0.y + hqv[j * 8 + 1]) * mlpv[j * 8 + 1];
            sum += ftanh_fast(f1.x + hqv[j * 8 + 2]) * mlpv[j * 8 + 2];
            sum += ftanh_fast(f1.y + hqv[j * 8 + 3]) * mlpv[j * 8 + 3];
            sum += ftanh_fast(f2.x + hqv[j * 8 + 4]) * mlpv[j * 8 + 4];
            sum += ftanh_fast(f2.y + hqv[j * 8 + 5]) * mlpv[j * 8 + 5];
            sum += ftanh_fast(f3.x + hqv[j * 8 + 6]) * mlpv[j * 8 + 6];
            sum += ftanh_fast(f3.y + hqv[j * 8 + 7]) * mlpv[j * 8 + 7];
        }
        #pragma unroll
        for (int o = 16; o; o >>= 1) sum += __shfl_xor_sync(0xffffffffu, sum, o);
        if (lane == 0) sc[s] = sum;
    }
    __syncthreads();

    // softmax over S
    float v = (tid < Sdim) ? sc[tid] : -1e30f;
    float mx = blockReduceMax(v, red);
    float e = (tid < Sdim) ? __expf(v - mx) : 0.f;
    float tot = blockReduceSum(e, red);
    if (tid < Sdim) sc[tid] = __fdividef(e, tot);
    __syncthreads();

    // Phase C: z[b,c] = sum_s alpha[s] * ctx[s,b,c]
    const int c4 = tid * 4;
    float4 acc = make_float4(0.f, 0.f, 0.f, 0.f);
    #pragma unroll 4
    for (int s = 0; s < Sdim; s++) {
        float a = sc[s];
        uint2 u = *(const uint2*)&g_ctx_bf16[((size_t)s * Bn + b) * Cdim + c4];
        float2 f0 = __bfloat1622float2(*(__nv_bfloat162*)&u.x);
        float2 f1 = __bfloat1622float2(*(__nv_bfloat162*)&u.y);
        acc.x = fmaf(a, f0.x, acc.x); acc.y = fmaf(a, f0.y, acc.y);
        acc.z = fmaf(a, f1.x, acc.z); acc.w = fmaf(a, f1.y, acc.w);
    }
    *(float4*)&g_z[b * Cdim + c4] = acc;
}

// ---------------- per-step elementwise kernels --------------------------------
__global__ void k_gru(const float* __restrict__ b_ih, const float* __restrict__ b_hh) {
    const int i = blockIdx.x * 256 + threadIdx.x;
    const int b = i >> 10, j = i & (Hdim - 1);
    float ir = b_ih[j], iz = b_ih[Hdim + j], in_ = b_ih[2 * Hdim + j];
    #pragma unroll
    for (int p = 0; p < 4; p++) {
        const float* g = g_gi_part + ((size_t)p * Bn + b) * 3 * Hdim;
        ir += g[j]; iz += g[Hdim + j]; in_ += g[2 * Hdim + j];
    }
    float hr = b_hh[j], hz = b_hh[Hdim + j], hn = b_hh[2 * Hdim + j];
    #pragma unroll
    for (int p = 0; p < 4; p++) {
        const float* g = g_gh_part + ((size_t)p * Bn + b) * 3 * Hdim;
        hr += g[j]; hz += g[Hdim + j]; hn += g[2 * Hdim + j];
    }
    float r = fsig(ir + hr);
    float zz = fsig(iz + hz);
    float n = ftanh(in_ + r * hn);
    float hold = g_h[i];
    g_h[i] = (1.f - zz) * n + zz * hold;
}

__global__ void k_pvec(const float* __restrict__ embW, const int* __restrict__ y,
                       const float* __restrict__ h2o_b, const float* __restrict__ octx_b, int t) {
    const int i = blockIdx.x * 256 + threadIdx.x;
    const int b = i >> 9, e = i & (Edim - 1);
    float o1 = h2o_b[e], o2 = octx_b[e];
    #pragma unroll
    for (int p = 0; p < 4; p++) {
        o1 += g_o1_part[p * Bn * Edim + i];
        o2 += g_o2_part[p * Bn * Edim + i];
    }
    float l = ftanh(o1);
    l += embW[(size_t)y[t * Bn + b] * Edim + e];
    l += o2;
    g_p_bf16[i] = __float2bfloat16_rn(ftanh(l));
}

__global__ __launch_bounds__(512) void k_nll(const int* __restrict__ y,
                                             const float* __restrict__ bias, int t) {
    const int b = blockIdx.x;
    const float* __restrict__ row = g_logits + (size_t)b * Vdim;
    __shared__ float red[16];
    float m = -1e30f;
    for (int v = threadIdx.x; v < Vdim; v += 512) m = fmaxf(m, row[v] + bias[v]);
    float mx = blockReduceMax(m, red);
    float s = 0.f;
    for (int v = threadIdx.x; v < Vdim; v += 512) s += __expf(row[v] + bias[v] - mx);
    float tot = blockReduceSum(s, red);
    if (threadIdx.x == 0) {
        int tgt = y[(t + 1) * Bn + b];
        float lse = mx + logf(tot);
        g_nll[t * Bn + b] = (tgt != 0) ? (lse - (row[tgt] + bias[tgt])) : 0.f;
    }
}

__global__ void k_final(float* __restrict__ out) {
    __shared__ float red[8];
    float s = 0.f;
    for (int i = threadIdx.x; i < NSTEP * Bn; i += 256) s += g_nll[i];
    float tot = blockReduceSum(s, red);
    if (threadIdx.x == 0) out[0] = tot;
}

// ---------------- launch ------------------------------------------------------
extern "C" void kernel_launch(void* const* d_in, const int* in_sizes, int n_in,
                              void* d_out, int out_size) {
    const float* ctx         = (const float*)d_in[0];
    const int*   y           = (const int*)  d_in[1];
    const float* embW        = (const float*)d_in[2];
    const float* att_ctx2ctx = (const float*)d_in[3];
    const float* att_hid2ctx = (const float*)d_in[4];
    const float* att_mlp     = (const float*)d_in[5];
    const float* gru_W_ih    = (const float*)d_in[6];
    const float* gru_b_ih    = (const float*)d_in[7];
    const float* gru_W_hh    = (const float*)d_in[8];
    const float* gru_b_hh    = (const float*)d_in[9];
    const float* h2o_W       = (const float*)d_in[10];
    const float* h2o_b       = (const float*)d_in[11];
    const float* octx_W      = (const float*)d_in[12];
    const float* octx_b      = (const float*)d_in[13];
    const float* o2p_W       = (const float*)d_in[14];
    const float* o2p_b       = (const float*)d_in[15];

    float *p_WctxT, *p_WhidT, *p_h, *p_hqp, *p_z, *p_gip, *p_ghp, *p_o1p, *p_o2p, *p_logits;
    __nv_bfloat16 *p_ctxpbf, *p_ctxbf, *p_Wbf, *p_pbf;
    cudaGetSymbolAddress((void**)&p_ctxpbf,  g_ctxp_bf16);
    cudaGetSymbolAddress((void**)&p_ctxbf,   g_ctx_bf16);
    cudaGetSymbolAddress((void**)&p_WctxT,   g_WctxT);
    cudaGetSymbolAddress((void**)&p_WhidT,   g_WhidT);
    cudaGetSymbolAddress((void**)&p_Wbf,     g_Wo2p_bf16);
    cudaGetSymbolAddress((void**)&p_pbf,     g_p_bf16);
    cudaGetSymbolAddress((void**)&p_h,       g_h);
    cudaGetSymbolAddress((void**)&p_hqp,     g_hq_part);
    cudaGetSymbolAddress((void**)&p_z,       g_z);
    cudaGetSymbolAddress((void**)&p_gip,     g_gi_part);
    cudaGetSymbolAddress((void**)&p_ghp,     g_gh_part);
    cudaGetSymbolAddress((void**)&p_o1p,     g_o1_part);
    cudaGetSymbolAddress((void**)&p_o2p,     g_o2_part);
    cudaGetSymbolAddress((void**)&p_logits,  g_logits);

    // one-time prep
    k_transpose<<<dim3(32, 32), dim3(32, 8)>>>(att_ctx2ctx, p_WctxT, Cdim, Cdim);
    k_transpose<<<dim3(32, 32), dim3(32, 8)>>>(att_hid2ctx, p_WhidT, Hdim, Cdim);
    k_cvt_bf16<<<((size_t)Vdim * Edim) / 1024, 256>>>(o2p_W, p_Wbf);
    k_cvt_bf16<<<((size_t)Sdim * Bn * Cdim) / 1024, 256>>>(ctx, p_ctxbf);
    k_zero_h<<<(Bn * Hdim) / 256, 256>>>();
    gemm_tf32_m128_bf16out<<<dim3(Cdim / 128, (Sdim * Bn) / 128), 256>>>(
        ctx, p_WctxT, p_ctxpbf, Cdim, Cdim);

    for (int t = 0; t < NSTEP; t++) {
        // hq partials = h @ att_hid2ctx (split-K 4)
        gemm_tf32_m64_sk<<<dim3(Cdim / 64, 1, 4), 256>>>(
            p_h, p_WhidT, p_hqp, p_h, p_WhidT, p_hqp, Cdim, Hdim, Hdim / 4);
        // fused attention (sums hq partials) -> z
        k_att<<<Bn, 256>>>(att_mlp);
        // gi partials (gathered A), gh partials
        gemm_tf32_gi_sk<<<dim3((3 * Hdim) / 64, 1, 4), 256>>>(
            embW, y, t, gru_W_ih, p_gip, 3 * Hdim, Edim + Cdim, (Edim + Cdim) / 4);
        gemm_tf32_m64_sk<<<dim3((3 * Hdim) / 64, 1, 4), 256>>>(
            p_h, gru_W_hh, p_ghp, p_h, gru_W_hh, p_ghp, 3 * Hdim, Hdim, Hdim / 4);
        k_gru<<<(Bn * Hdim) / 256, 256>>>(gru_b_ih, gru_b_hh);
        // o1/o2 partials (dual, split-K 4)
        gemm_tf32_m64_sk<<<dim3(Edim / 64, 2, 4), 256>>>(
            p_h, h2o_W, p_o1p, p_z, octx_W, p_o2p, Edim, Hdim, Hdim / 4);
        k_pvec<<<(Bn * Edim) / 256, 256>>>(embW, y, h2o_b, octx_b, t);
        gemm_bf16_logits<<<Vdim / 256, 256>>>(p_pbf, p_Wbf, p_logits, Vdim, Edim);
        k_nll<<<Bn, 512>>>(y, o2p_b, t);
    }
    k_final<<<1, 256>>>((float*)d_out);
}

// round 9
// speedup vs baseline: 3.5160x; 1.1763x over previous
#include <cuda_runtime.h>
#include <cuda_bf16.h>
#include <math.h>

#define Sdim 196
#define Bn   64
#define Cdim 1024
#define Hdim 1024
#define Edim 512
#define Vdim 32000
#define NSTEP 19
#define NVBLK (Vdim / 256)   // 125 logits blocks

// ---------------- scratch (device globals) -----------------------------------
__device__ __nv_bfloat16 g_ctxp_bf16[(size_t)Sdim * Bn * Cdim];
__device__ __nv_bfloat16 g_ctx_bf16[(size_t)Sdim * Bn * Cdim];
__device__ __nv_bfloat16 g_WctxT_bf16[Cdim * Cdim];
__device__ float g_WhidT[Hdim * Cdim];
__device__ __nv_bfloat16 g_Wo2p_bf16[(size_t)Vdim * Edim];
__device__ __nv_bfloat16 g_p_bf16[Bn * Edim];
__device__ float g_h[Bn * Hdim];
__device__ float g_hq_part[4 * Bn * Cdim];
__device__ float g_z[Bn * Cdim];
__device__ float g_gi_part[4 * Bn * 3 * Hdim];
__device__ float g_gh_part[4 * Bn * 3 * Hdim];
__device__ float g_o1_part[4 * Bn * Edim];
__device__ float g_o2_part[4 * Bn * Edim];
__device__ float g_pm[NVBLK * Bn];
__device__ float g_ps[NVBLK * Bn];
__device__ float g_ltgt[Bn];
__device__ float g_nll[NSTEP * Bn];

// ---------------- fast math ---------------------------------------------------
__device__ __forceinline__ float ftanh(float x) {
    float xc = fminf(fmaxf(x, -15.f), 15.f);
    float e = __expf(2.f * xc);
    return __fdividef(e - 1.f, e + 1.f);
}
__device__ __forceinline__ float ftanh_fast(float x) {
    float y;
    asm("tanh.approx.f32 %0, %1;" : "=f"(y) : "f"(x));
    return y;
}
__device__ __forceinline__ float fsig(float x) {
    return __fdividef(1.f, 1.f + __expf(-x));
}
__device__ __forceinline__ float to_tf32(float x) {
    unsigned u;
    asm("cvt.rna.tf32.f32 %0, %1;" : "=r"(u) : "f"(x));
    return __uint_as_float(u);
}
__device__ __forceinline__ void mma_tf32(float* d, const float* a4, const float* b2) {
    asm volatile(
        "mma.sync.aligned.m16n8k8.row.col.f32.tf32.tf32.f32 "
        "{%0,%1,%2,%3}, {%4,%5,%6,%7}, {%8,%9}, {%0,%1,%2,%3};\n"
        : "+f"(d[0]), "+f"(d[1]), "+f"(d[2]), "+f"(d[3])
        : "r"(__float_as_uint(a4[0])), "r"(__float_as_uint(a4[1])),
          "r"(__float_as_uint(a4[2])), "r"(__float_as_uint(a4[3])),
          "r"(__float_as_uint(b2[0])), "r"(__float_as_uint(b2[1])));
}
__device__ __forceinline__ void mma_bf16(float* d, const unsigned* a4, const unsigned* b2) {
    asm volatile(
        "mma.sync.aligned.m16n8k16.row.col.f32.bf16.bf16.f32 "
        "{%0,%1,%2,%3}, {%4,%5,%6,%7}, {%8,%9}, {%0,%1,%2,%3};\n"
        : "+f"(d[0]), "+f"(d[1]), "+f"(d[2]), "+f"(d[3])
        : "r"(a4[0]), "r"(a4[1]), "r"(a4[2]), "r"(a4[3]), "r"(b2[0]), "r"(b2[1]));
}
// online (m,s) update with value v
__device__ __forceinline__ void lse_upd(float& m, float& s, float v) {
    if (v > m) { s = s * __expf(m - v) + 1.f; m = v; }
    else       { s += __expf(v - m); }
}
// combine two (m,s) pairs (deterministic given fixed order)
__device__ __forceinline__ void lse_comb(float& m, float& s, float m2, float s2) {
    float M = fmaxf(m, m2);
    s = s * __expf(m - M) + s2 * __expf(m2 - M);
    m = M;
}

// ---------------- block reductions (fixed order) ------------------------------
__device__ __forceinline__ float blockReduceSum(float v, float* red) {
    #pragma unroll
    for (int o = 16; o; o >>= 1) v += __shfl_xor_sync(0xffffffffu, v, o);
    if ((threadIdx.x & 31) == 0) red[threadIdx.x >> 5] = v;
    __syncthreads();
    float t = 0.f;
    int nw = blockDim.x >> 5;
    for (int i = 0; i < nw; i++) t += red[i];
    __syncthreads();
    return t;
}
__device__ __forceinline__ float blockReduceMax(float v, float* red) {
    #pragma unroll
    for (int o = 16; o; o >>= 1) v = fmaxf(v, __shfl_xor_sync(0xffffffffu, v, o));
    if ((threadIdx.x & 31) == 0) red[threadIdx.x >> 5] = v;
    __syncthreads();
    float t = red[0];
    int nw = blockDim.x >> 5;
    for (int i = 1; i < nw; i++) t = fmaxf(t, red[i]);
    __syncthreads();
    return t;
}

// ---------------- one-time prep kernels ---------------------------------------
__global__ void k_transpose(const float* __restrict__ in, float* __restrict__ out, int R, int Ccols) {
    __shared__ float t[32][33];
    int c0 = blockIdx.x * 32, r0 = blockIdx.y * 32;
    #pragma unroll
    for (int i = 0; i < 4; i++)
        t[threadIdx.y + i * 8][threadIdx.x] = in[(size_t)(r0 + threadIdx.y + i * 8) * Ccols + c0 + threadIdx.x];
    __syncthreads();
    #pragma unroll
    for (int i = 0; i < 4; i++)
        out[(size_t)(c0 + threadIdx.y + i * 8) * R + r0 + threadIdx.x] = t[threadIdx.x][threadIdx.y + i * 8];
}
__global__ void k_transpose_bf16(const float* __restrict__ in, __nv_bfloat16* __restrict__ out, int R, int Ccols) {
    __shared__ float t[32][33];
    int c0 = blockIdx.x * 32, r0 = blockIdx.y * 32;
    #pragma unroll
    for (int i = 0; i < 4; i++)
        t[threadIdx.y + i * 8][threadIdx.x] = in[(size_t)(r0 + threadIdx.y + i * 8) * Ccols + c0 + threadIdx.x];
    __syncthreads();
    #pragma unroll
    for (int i = 0; i < 4; i++)
        out[(size_t)(c0 + threadIdx.y + i * 8) * R + r0 + threadIdx.x] =
            __float2bfloat16_rn(t[threadIdx.x][threadIdx.y + i * 8]);
}
__global__ void k_cvt_bf16(const float* __restrict__ in, __nv_bfloat16* __restrict__ out) {
    size_t i = ((size_t)blockIdx.x * 256 + threadIdx.x) * 4;
    float4 v = *(const float4*)&in[i];
    __nv_bfloat162* o = (__nv_bfloat162*)&out[i];
    o[0] = __floats2bfloat162_rn(v.x, v.y);
    o[1] = __floats2bfloat162_rn(v.z, v.w);
}
__global__ void k_zero_h() { g_h[blockIdx.x * 256 + threadIdx.x] = 0.f; }

// ============ BF16 NT GEMM, 128x128 tile, bf16 out (ctx_proj) =================
__global__ __launch_bounds__(256) void gemm_bf16_m128(
    const __nv_bfloat16* __restrict__ A, const __nv_bfloat16* __restrict__ B,
    __nv_bfloat16* __restrict__ C, int N, int K) {
    __shared__ __nv_bfloat16 As[128][72];
    __shared__ __nv_bfloat16 Bs[128][72];
    const int row0 = blockIdx.y * 128, col0 = blockIdx.x * 128;
    const int tid = threadIdx.x;
    const int wid = tid >> 5, lane = tid & 31;
    const int gID = lane >> 2, tig = lane & 3;
    const int m0w = (wid >> 2) * 64, n0w = (wid & 3) * 32;
    const int lrow = tid >> 1, lcol = (tid & 1) * 32;
    float acc[4][4][4] = {};
    for (int k0 = 0; k0 < K; k0 += 64) {
        #pragma unroll
        for (int i = 0; i < 4; i++) {
            *(uint4*)&As[lrow][lcol + i * 8] = *(const uint4*)&A[(size_t)(row0 + lrow) * K + k0 + lcol + i * 8];
            *(uint4*)&Bs[lrow][lcol + i * 8] = *(const uint4*)&B[(size_t)(col0 + lrow) * K + k0 + lcol + i * 8];
        }
        __syncthreads();
        #pragma unroll
        for (int kk = 0; kk < 4; kk++) {
            const int kb = kk * 16;
            unsigned af[4][4], bf[4][2];
            #pragma unroll
            for (int mi = 0; mi < 4; mi++) {
                int r = m0w + mi * 16 + gID;
                int c = kb + tig * 2;
                af[mi][0] = *(const unsigned*)&As[r][c];
                af[mi][1] = *(const unsigned*)&As[r + 8][c];
                af[mi][2] = *(const unsigned*)&As[r][c + 8];
                af[mi][3] = *(const unsigned*)&As[r + 8][c + 8];
            }
            #pragma unroll
            for (int ni = 0; ni < 4; ni++) {
                int n = n0w + ni * 8 + gID;
                int c = kb + tig * 2;
                bf[ni][0] = *(const unsigned*)&Bs[n][c];
                bf[ni][1] = *(const unsigned*)&Bs[n][c + 8];
            }
            #pragma unroll
            for (int mi = 0; mi < 4; mi++)
                #pragma unroll
                for (int ni = 0; ni < 4; ni++)
                    mma_bf16(acc[mi][ni], af[mi], bf[ni]);
        }
        __syncthreads();
    }
    #pragma unroll
    for (int mi = 0; mi < 4; mi++)
        #pragma unroll
        for (int ni = 0; ni < 4; ni++) {
            int r = row0 + m0w + mi * 16 + gID;
            int c = col0 + n0w + ni * 8 + tig * 2;
            *(__nv_bfloat162*)&C[(size_t)r * N + c]       = __floats2bfloat162_rn(acc[mi][ni][0], acc[mi][ni][1]);
            *(__nv_bfloat162*)&C[(size_t)(r + 8) * N + c] = __floats2bfloat162_rn(acc[mi][ni][2], acc[mi][ni][3]);
        }
}

// ============ TF32 NT GEMM, M=64, split-K, dual problem =======================
__global__ __launch_bounds__(256) void gemm_tf32_m64_sk(
    const float* __restrict__ A0, const float* __restrict__ B0, float* __restrict__ C0,
    const float* __restrict__ A1, const float* __restrict__ B1, float* __restrict__ C1,
    int N, int K, int kChunk) {
    const float* A = A0; const float* B = B0; float* C = C0;
    if (blockIdx.y == 1) { A = A1; B = B1; C = C1; }
    __shared__ float As[64][36];
    __shared__ float Bs[64][36];
    const int col0 = blockIdx.x * 64;
    const int kbase = blockIdx.z * kChunk;
    const int tid = threadIdx.x;
    const int wid = tid >> 5, lane = tid & 31;
    const int gID = lane >> 2, tig = lane & 3;
    const int lrow = tid >> 2, lseg = (tid & 3) * 8;
    float acc[4][4] = {};
    for (int kt = 0; kt < kChunk; kt += 32) {
        const int k0 = kbase + kt;
        #pragma unroll
        for (int i = 0; i < 2; i++) {
            float4 a = *(const float4*)&A[(size_t)lrow * K + k0 + lseg + i * 4];
            a.x = to_tf32(a.x); a.y = to_tf32(a.y); a.z = to_tf32(a.z); a.w = to_tf32(a.w);
            *(float4*)&As[lrow][lseg + i * 4] = a;
            float4 b = *(const float4*)&B[(size_t)(col0 + lrow) * K + k0 + lseg + i * 4];
            b.x = to_tf32(b.x); b.y = to_tf32(b.y); b.z = to_tf32(b.z); b.w = to_tf32(b.w);
            *(float4*)&Bs[lrow][lseg + i * 4] = b;
        }
        __syncthreads();
        #pragma unroll
        for (int kk = 0; kk < 4; kk++) {
            const int kb = kk * 8;
            float bfv[2];
            bfv[0] = Bs[wid * 8 + gID][kb + tig]; bfv[1] = Bs[wid * 8 + gID][kb + tig + 4];
            #pragma unroll
            for (int mi = 0; mi < 4; mi++) {
                float af[4];
                int r = mi * 16 + gID;
                af[0] = As[r][kb + tig];     af[1] = As[r + 8][kb + tig];
                af[2] = As[r][kb + tig + 4]; af[3] = As[r + 8][kb + tig + 4];
                mma_tf32(acc[mi], af, bfv);
            }
        }
        __syncthreads();
    }
    float* Cp = C + (size_t)blockIdx.z * 64 * N;
    #pragma unroll
    for (int mi = 0; mi < 4; mi++) {
        int r = mi * 16 + gID;
        int c = col0 + wid * 8 + tig * 2;
        *(float2*)&Cp[(size_t)r * N + c]       = make_float2(acc[mi][0], acc[mi][1]);
        *(float2*)&Cp[(size_t)(r + 8) * N + c] = make_float2(acc[mi][2], acc[mi][3]);
    }
}

// ============ merged GRU GEMMs: y=0 -> gi (A gathered), y=1 -> gh =============
__global__ __launch_bounds__(256) void gemm_gigh_sk(
    const float* __restrict__ embW, const int* __restrict__ y, int t,
    const float* __restrict__ Wih, float* __restrict__ Cgi,
    const float* __restrict__ Whh, float* __restrict__ Cgh) {
    const bool is_gi = (blockIdx.y == 0);
    const int K      = is_gi ? (Edim + Cdim) : Hdim;
    const int kChunk = is_gi ? ((Edim + Cdim) / 4) : (Hdim / 4);
    const float* B   = is_gi ? Wih : Whh;
    float* C         = is_gi ? Cgi : Cgh;
    const int N = 3 * Hdim;
    __shared__ float As[64][36];
    __shared__ float Bs[64][36];
    const int col0 = blockIdx.x * 64;
    const int kbase = blockIdx.z * kChunk;
    const int tid = threadIdx.x;
    const int wid = tid >> 5, lane = tid & 31;
    const int gID = lane >> 2, tig = lane & 3;
    const int lrow = tid >> 2, lseg = (tid & 3) * 8;
    const int yid = is_gi ? y[t * Bn + lrow] : 0;
    float acc[4][4] = {};
    for (int kt = 0; kt < kChunk; kt += 32) {
        const int k0 = kbase + kt;
        const float* Arow;
        if (is_gi) Arow = (k0 < Edim) ? &embW[(size_t)yid * Edim + k0]
                                      : &g_z[lrow * Cdim + (k0 - Edim)];
        else       Arow = &g_h[lrow * Hdim + k0];
        #pragma unroll
        for (int i = 0; i < 2; i++) {
            float4 a = *(const float4*)&Arow[lseg + i * 4];
            a.x = to_tf32(a.x); a.y = to_tf32(a.y); a.z = to_tf32(a.z); a.w = to_tf32(a.w);
            *(float4*)&As[lrow][lseg + i * 4] = a;
            float4 b = *(const float4*)&B[(size_t)(col0 + lrow) * K + k0 + lseg + i * 4];
            b.x = to_tf32(b.x); b.y = to_tf32(b.y); b.z = to_tf32(b.z); b.w = to_tf32(b.w);
            *(float4*)&Bs[lrow][lseg + i * 4] = b;
        }
        __syncthreads();
        #pragma unroll
        for (int kk = 0; kk < 4; kk++) {
            const int kb = kk * 8;
            float bfv[2];
            bfv[0] = Bs[wid * 8 + gID][kb + tig]; bfv[1] = Bs[wid * 8 + gID][kb + tig + 4];
            #pragma unroll
            for (int mi = 0; mi < 4; mi++) {
                float af[4];
                int r = mi * 16 + gID;
                af[0] = As[r][kb + tig];     af[1] = As[r + 8][kb + tig];
                af[2] = As[r][kb + tig + 4]; af[3] = As[r + 8][kb + tig + 4];
                mma_tf32(acc[mi], af, bfv);
            }
        }
        __syncthreads();
    }
    float* Cp = C + (size_t)blockIdx.z * 64 * N;
    #pragma unroll
    for (int mi = 0; mi < 4; mi++) {
        int r = mi * 16 + gID;
        int c = col0 + wid * 8 + tig * 2;
        *(float2*)&Cp[(size_t)r * N + c]       = make_float2(acc[mi][0], acc[mi][1]);
        *(float2*)&Cp[(size_t)(r + 8) * N + c] = make_float2(acc[mi][2], acc[mi][3]);
    }
}

// ============ BF16 logits GEMM + fused partial NLL ============================
// Computes per-row online (max, expsum) over this block's 256 vocab cols
// (bias included) + captures the target logit. No logits written to gmem.
// smem: As (9216B) + Bs (36864B); the (m,s) staging buffers overlay As after
// the mainloop (fenced by the loop's final __syncthreads + one more below).
__global__ __launch_bounds__(256) void gemm_bf16_logits_nll(
    const __nv_bfloat16* __restrict__ A, const __nv_bfloat16* __restrict__ B,
    const float* __restrict__ bias, const int* __restrict__ y, int t, int K) {
    __shared__ __align__(16) unsigned char sbuf[9216 + 36864];
    __nv_bfloat16 (*As)[72] = reinterpret_cast<__nv_bfloat16(*)[72]>(sbuf);
    __nv_bfloat16 (*Bs)[72] = reinterpret_cast<__nv_bfloat16(*)[72]>(sbuf + 9216);
    float (*sm)[8] = reinterpret_cast<float(*)[8]>(sbuf);           // overlays As
    float (*ss)[8] = reinterpret_cast<float(*)[8]>(sbuf + 2048);    // overlays As
    const int col0 = blockIdx.x * 256;
    const int tid = threadIdx.x;
    const int wid = tid >> 5, lane = tid & 31;
    const int gID = lane >> 2, tig = lane & 3;
    const int n0w = wid * 32;
    float acc[4][4][4] = {};
    for (int k0 = 0; k0 < K; k0 += 64) {
        {
            int ar = tid >> 2, as = (tid & 3) * 16;
            *(uint4*)&As[ar][as]     = *(const uint4*)&A[(size_t)ar * K + k0 + as];
            *(uint4*)&As[ar][as + 8] = *(const uint4*)&A[(size_t)ar * K + k0 + as + 8];
            #pragma unroll
            for (int i = 0; i < 8; i++)
                *(uint4*)&Bs[tid][i * 8] = *(const uint4*)&B[(size_t)(col0 + tid) * K + k0 + i * 8];
        }
        __syncthreads();
        #pragma unroll
        for (int kk = 0; kk < 4; kk++) {
            const int kb = kk * 16;
            unsigned af[4][4], bf[4][2];
            #pragma unroll
            for (int mi = 0; mi < 4; mi++) {
                int r = mi * 16 + gID;
                int c = kb + tig * 2;
                af[mi][0] = *(const unsigned*)&As[r][c];
                af[mi][1] = *(const unsigned*)&As[r + 8][c];
                af[mi][2] = *(const unsigned*)&As[r][c + 8];
                af[mi][3] = *(const unsigned*)&As[r + 8][c + 8];
            }
            #pragma unroll
            for (int ni = 0; ni < 4; ni++) {
                int n = n0w + ni * 8 + gID;
                int c = kb + tig * 2;
                bf[ni][0] = *(const unsigned*)&Bs[n][c];
                bf[ni][1] = *(const unsigned*)&Bs[n][c + 8];
            }
            #pragma unroll
            for (int mi = 0; mi < 4; mi++)
                #pragma unroll
                for (int ni = 0; ni < 4; ni++)
                    mma_bf16(acc[mi][ni], af[mi], bf[ni]);
        }
        __syncthreads();
    }
    // epilogue: bias + per-row online (m, s) + target capture.
    // As region is dead now (last loop iteration ended with __syncthreads).
    #pragma unroll
    for (int mi = 0; mi < 4; mi++) {
        const int r  = mi * 16 + gID;     // batch row (0..63)
        const int r2 = r + 8;
        const int tgt  = y[(t + 1) * Bn + r];
        const int tgt2 = y[(t + 1) * Bn + r2];
        float m1 = -1e30f, s1 = 0.f, m2 = -1e30f, s2 = 0.f;
        #pragma unroll
        for (int ni = 0; ni < 4; ni++) {
            int c = col0 + n0w + ni * 8 + tig * 2;
            float b0 = bias[c], b1 = bias[c + 1];
            float v0 = acc[mi][ni][0] + b0, v1 = acc[mi][ni][1] + b1;
            float v2 = acc[mi][ni][2] + b0, v3 = acc[mi][ni][3] + b1;
            if (c == tgt)      g_ltgt[r]  = v0;
            if (c + 1 == tgt)  g_ltgt[r]  = v1;
            if (c == tgt2)     g_ltgt[r2] = v2;
            if (c + 1 == tgt2) g_ltgt[r2] = v3;
            lse_upd(m1, s1, v0); lse_upd(m1, s1, v1);
            lse_upd(m2, s2, v2); lse_upd(m2, s2, v3);
        }
        // combine across the 4 lanes sharing this row (tig group)
        #pragma unroll
        for (int off = 1; off <= 2; off <<= 1) {
            float om = __shfl_xor_sync(0xffffffffu, m1, off);
            float os = __shfl_xor_sync(0xffffffffu, s1, off);
            lse_comb(m1, s1, om, os);
            om = __shfl_xor_sync(0xffffffffu, m2, off);
            os = __shfl_xor_sync(0xffffffffu, s2, off);
            lse_comb(m2, s2, om, os);
        }
        if (tig == 0) {
            sm[r][wid] = m1; ss[r][wid] = s1;
            sm[r2][wid] = m2; ss[r2][wid] = s2;
        }
    }
    __syncthreads();
    if (tid < 64) {
        float M = sm[tid][0], S = ss[tid][0];
        #pragma unroll
        for (int w = 1; w < 8; w++) lse_comb(M, S, sm[tid][w], ss[tid][w]);
        g_pm[blockIdx.x * Bn + tid] = M;
        g_ps[blockIdx.x * Bn + tid] = S;
    }
}

// ============ tiny NLL reduce over NVBLK partials per batch row ===============
__global__ __launch_bounds__(128) void k_nll2(const int* __restrict__ y, int t) {
    const int b = blockIdx.x;
    const int tid = threadIdx.x;
    __shared__ float smm[4], sss[4];
    float m = -1e30f, s = 0.f;
    for (int i = tid; i < NVBLK; i += 128)
        lse_comb(m, s, g_pm[i * Bn + b], g_ps[i * Bn + b]);
    #pragma unroll
    for (int off = 16; off; off >>= 1) {
        float om = __shfl_xor_sync(0xffffffffu, m, off);
        float os = __shfl_xor_sync(0xffffffffu, s, off);
        lse_comb(m, s, om, os);
    }
    if ((tid & 31) == 0) { smm[tid >> 5] = m; sss[tid >> 5] = s; }
    __syncthreads();
    if (tid == 0) {
        float M = smm[0], S = sss[0];
        #pragma unroll
        for (int w = 1; w < 4; w++) lse_comb(M, S, smm[w], sss[w]);
        int tgt = y[(t + 1) * Bn + b];
        float lse = M + logf(S);
        g_nll[t * Bn + b] = (tgt != 0) ? (lse - g_ltgt[b]) : 0.f;
    }
}

// ============ fused attention: scores + softmax + z (one block per b) =========
__global__ __launch_bounds__(256) void k_att(const float* __restrict__ mlp) {
    const int b = blockIdx.x;
    const int tid = threadIdx.x;
    const int wid = tid >> 5, lane = tid & 31;
    __shared__ float sc[200];
    __shared__ float red[8];
    float hqv[32], mlpv[32];
    #pragma unroll
    for (int j = 0; j < 4; j++) {
        #pragma unroll
        for (int u = 0; u < 8; u++) {
            int m = lane * 8 + j * 256 + u;
            float v = g_hq_part[b * Cdim + m]
                    + g_hq_part[(Bn + b) * Cdim + m]
                    + g_hq_part[(2 * Bn + b) * Cdim + m]
                    + g_hq_part[(3 * Bn + b) * Cdim + m];
            hqv[j * 8 + u] = v;
            mlpv[j * 8 + u] = mlp[m];
        }
    }
    for (int s = wid; s < Sdim; s += 8) {
        const __nv_bfloat16* row = g_ctxp_bf16 + ((size_t)s * Bn + b) * Cdim;
        float sum = 0.f;
        #pragma unroll
        for (int j = 0; j < 4; j++) {
            int m = lane * 8 + j * 256;
            uint4 u = *(const uint4*)&row[m];
            float2 f0 = __bfloat1622float2(*(__nv_bfloat162*)&u.x);
            float2 f1 = __bfloat1622float2(*(__nv_bfloat162*)&u.y);
            float2 f2 = __bfloat1622float2(*(__nv_bfloat162*)&u.z);
            float2 f3 = __bfloat1622float2(*(__nv_bfloat162*)&u.w);
            sum += ftanh_fast(f0.x + hqv[j * 8 + 0]) * mlpv[j * 8 + 0];
            sum += ftanh_fast(f0.y + hqv[j * 8 + 1]) * mlpv[j * 8 + 1];
            sum += ftanh_fast(f1.x + hqv[j * 8 + 2]) * mlpv[j * 8 + 2];
            sum += ftanh_fast(f1.y + hqv[j * 8 + 3]) * mlpv[j * 8 + 3];
            sum += ftanh_fast(f2.x + hqv[j * 8 + 4]) * mlpv[j * 8 + 4];
            sum += ftanh_fast(f2.y + hqv[j * 8 + 5]) * mlpv[j * 8 + 5];
            sum += ftanh_fast(f3.x + hqv[j * 8 + 6]) * mlpv[j * 8 + 6];
            sum += ftanh_fast(f3.y + hqv[j * 8 + 7]) * mlpv[j * 8 + 7];
        }
        #pragma unroll
        for (int o = 16; o; o >>= 1) sum += __shfl_xor_sync(0xffffffffu, sum, o);
        if (lane == 0) sc[s] = sum;
    }
    __syncthreads();
    float v = (tid < Sdim) ? sc[tid] : -1e30f;
    float mx = blockReduceMax(v, red);
    float e = (tid < Sdim) ? __expf(v - mx) : 0.f;
    float tot = blockReduceSum(e, red);
    if (tid < Sdim) sc[tid] = __fdividef(e, tot);
    __syncthreads();
    const int c4 = tid * 4;
    float4 acc = make_float4(0.f, 0.f, 0.f, 0.f);
    #pragma unroll 4
    for (int s = 0; s < Sdim; s++) {
        float a = sc[s];
        uint2 u = *(const uint2*)&g_ctx_bf16[((size_t)s * Bn + b) * Cdim + c4];
        float2 f0 = __bfloat1622float2(*(__nv_bfloat162*)&u.x);
        float2 f1 = __bfloat1622float2(*(__nv_bfloat162*)&u.y);
        acc.x = fmaf(a, f0.x, acc.x); acc.y = fmaf(a, f0.y, acc.y);
        acc.z = fmaf(a, f1.x, acc.z); acc.w = fmaf(a, f1.y, acc.w);
    }
    *(float4*)&g_z[b * Cdim + c4] = acc;
}

// ---------------- per-step elementwise kernels --------------------------------
__global__ void k_gru(const float* __restrict__ b_ih, const float* __restrict__ b_hh) {
    const int i = blockIdx.x * 256 + threadIdx.x;
    const int b = i >> 10, j = i & (Hdim - 1);
    float ir = b_ih[j], iz = b_ih[Hdim + j], in_ = b_ih[2 * Hdim + j];
    #pragma unroll
    for (int p = 0; p < 4; p++) {
        const float* g = g_gi_part + ((size_t)p * Bn + b) * 3 * Hdim;
        ir += g[j]; iz += g[Hdim + j]; in_ += g[2 * Hdim + j];
    }
    float hr = b_hh[j], hz = b_hh[Hdim + j], hn = b_hh[2 * Hdim + j];
    #pragma unroll
    for (int p = 0; p < 4; p++) {
        const float* g = g_gh_part + ((size_t)p * Bn + b) * 3 * Hdim;
        hr += g[j]; hz += g[Hdim + j]; hn += g[2 * Hdim + j];
    }
    float r = fsig(ir + hr);
    float zz = fsig(iz + hz);
    float n = ftanh(in_ + r * hn);
    float hold = g_h[i];
    g_h[i] = (1.f - zz) * n + zz * hold;
}

__global__ void k_pvec(const float* __restrict__ embW, const int* __restrict__ y,
                       const float* __restrict__ h2o_b, const float* __restrict__ octx_b, int t) {
    const int i = blockIdx.x * 256 + threadIdx.x;
    const int b = i >> 9, e = i & (Edim - 1);
    float o1 = h2o_b[e], o2 = octx_b[e];
    #pragma unroll
    for (int p = 0; p < 4; p++) {
        o1 += g_o1_part[p * Bn * Edim + i];
        o2 += g_o2_part[p * Bn * Edim + i];
    }
    float l = ftanh(o1);
    l += embW[(size_t)y[t * Bn + b] * Edim + e];
    l += o2;
    g_p_bf16[i] = __float2bfloat16_rn(ftanh(l));
}

__global__ void k_final(float* __restrict__ out) {
    __shared__ float red[8];
    float s = 0.f;
    for (int i = threadIdx.x; i < NSTEP * Bn; i += 256) s += g_nll[i];
    float tot = blockReduceSum(s, red);
    if (threadIdx.x == 0) out[0] = tot;
}

// ---------------- launch ------------------------------------------------------
extern "C" void kernel_launch(void* const* d_in, const int* in_sizes, int n_in,
                              void* d_out, int out_size) {
    const float* ctx         = (const float*)d_in[0];
    const int*   y           = (const int*)  d_in[1];
    const float* embW        = (const float*)d_in[2];
    const float* att_ctx2ctx = (const float*)d_in[3];
    const float* att_hid2ctx = (const float*)d_in[4];
    const float* att_mlp     = (const float*)d_in[5];
    const float* gru_W_ih    = (const float*)d_in[6];
    const float* gru_b_ih    = (const float*)d_in[7];
    const float* gru_W_hh    = (const float*)d_in[8];
    const float* gru_b_hh    = (const float*)d_in[9];
    const float* h2o_W       = (const float*)d_in[10];
    const float* h2o_b       = (const float*)d_in[11];
    const float* octx_W      = (const float*)d_in[12];
    const float* octx_b      = (const float*)d_in[13];
    const float* o2p_W       = (const float*)d_in[14];
    const float* o2p_b       = (const float*)d_in[15];

    float *p_WhidT, *p_h, *p_hqp, *p_z, *p_gip, *p_ghp, *p_o1p, *p_o2p;
    __nv_bfloat16 *p_ctxpbf, *p_ctxbf, *p_WctxTbf, *p_Wbf, *p_pbf;
    cudaGetSymbolAddress((void**)&p_ctxpbf,  g_ctxp_bf16);
    cudaGetSymbolAddress((void**)&p_ctxbf,   g_ctx_bf16);
    cudaGetSymbolAddress((void**)&p_WctxTbf, g_WctxT_bf16);
    cudaGetSymbolAddress((void**)&p_WhidT,   g_WhidT);
    cudaGetSymbolAddress((void**)&p_Wbf,     g_Wo2p_bf16);
    cudaGetSymbolAddress((void**)&p_pbf,     g_p_bf16);
    cudaGetSymbolAddress((void**)&p_h,       g_h);
    cudaGetSymbolAddress((void**)&p_hqp,     g_hq_part);
    cudaGetSymbolAddress((void**)&p_z,       g_z);
    cudaGetSymbolAddress((void**)&p_gip,     g_gi_part);
    cudaGetSymbolAddress((void**)&p_ghp,     g_gh_part);
    cudaGetSymbolAddress((void**)&p_o1p,     g_o1_part);
    cudaGetSymbolAddress((void**)&p_o2p,     g_o2_part);

    // one-time prep
    k_cvt_bf16<<<((size_t)Sdim * Bn * Cdim) / 1024, 256>>>(ctx, p_ctxbf);
    k_transpose_bf16<<<dim3(32, 32), dim3(32, 8)>>>(att_ctx2ctx, p_WctxTbf, Cdim, Cdim);
    k_transpose<<<dim3(32, 32), dim3(32, 8)>>>(att_hid2ctx, p_WhidT, Hdim, Cdim);
    k_cvt_bf16<<<((size_t)Vdim * Edim) / 1024, 256>>>(o2p_W, p_Wbf);
    k_zero_h<<<(Bn * Hdim) / 256, 256>>>();
    // ctx_proj (bf16 mma, bf16 out)
    gemm_bf16_m128<<<dim3(Cdim / 128, (Sdim * Bn) / 128), 256>>>(
        p_ctxbf, p_WctxTbf, p_ctxpbf, Cdim, Cdim);

    for (int t = 0; t < NSTEP; t++) {
        gemm_tf32_m64_sk<<<dim3(Cdim / 64, 1, 4), 256>>>(
            p_h, p_WhidT, p_hqp, p_h, p_WhidT, p_hqp, Cdim, Hdim, Hdim / 4);
        k_att<<<Bn, 256>>>(att_mlp);
        gemm_gigh_sk<<<dim3((3 * Hdim) / 64, 2, 4), 256>>>(
            embW, y, t, gru_W_ih, p_gip, gru_W_hh, p_ghp);
        k_gru<<<(Bn * Hdim) / 256, 256>>>(gru_b_ih, gru_b_hh);
        gemm_tf32_m64_sk<<<dim3(Edim / 64, 2, 4), 256>>>(
            p_h, h2o_W, p_o1p, p_z, octx_W, p_o2p, Edim, Hdim, Hdim / 4);
        k_pvec<<<(Bn * Edim) / 256, 256>>>(embW, y, h2o_b, octx_b, t);
        gemm_bf16_logits_nll<<<NVBLK, 256>>>(p_pbf, p_Wbf, o2p_b, y, t, Edim);
        k_nll2<<<Bn, 128>>>(y, t);
    }
    k_final<<<1, 256>>>((float*)d_out);
}

// round 10
// speedup vs baseline: 3.8599x; 1.0978x over previous
#include <cuda_runtime.h>
#include <cuda_bf16.h>
#include <math.h>

#define Sdim 196
#define Bn   64
#define Cdim 1024
#define Hdim 1024
#define Edim 512
#define Vdim 32000
#define NSTEP 19
#define NVBLK (Vdim / 256)   // 125 logits blocks

// ---------------- scratch (device globals) -----------------------------------
__device__ __nv_bfloat16 g_ctxp_bf16[(size_t)Sdim * Bn * Cdim];
__device__ __nv_bfloat16 g_ctx_bf16[(size_t)Sdim * Bn * Cdim];
__device__ __nv_bfloat16 g_WctxT_bf16[Cdim * Cdim];
__device__ __nv_bfloat16 g_WhidT_bf16[Hdim * Cdim];
__device__ __nv_bfloat16 g_Wih_bf16[3 * Hdim * (Edim + Cdim)];
__device__ __nv_bfloat16 g_Whh_bf16[3 * Hdim * Hdim];
__device__ __nv_bfloat16 g_h2o_bf16[Edim * Hdim];
__device__ __nv_bfloat16 g_octx_bf16[Edim * Cdim];
__device__ __nv_bfloat16 g_Wo2p_bf16[(size_t)Vdim * Edim];
__device__ __nv_bfloat16 g_p_bf16[Bn * Edim];
__device__ float g_h[Bn * Hdim];
__device__ float g_hq_part[4 * Bn * Cdim];
__device__ float g_z[Bn * Cdim];
__device__ float g_gi_part[4 * Bn * 3 * Hdim];
__device__ float g_gh_part[4 * Bn * 3 * Hdim];
__device__ float g_o1_part[4 * Bn * Edim];
__device__ float g_o2_part[4 * Bn * Edim];
__device__ float g_pm[NVBLK * Bn];
__device__ float g_ps[NVBLK * Bn];
__device__ float g_ltgt[Bn];
__device__ float g_nll[NSTEP * Bn];

// ---------------- fast math ---------------------------------------------------
__device__ __forceinline__ float ftanh(float x) {
    float xc = fminf(fmaxf(x, -15.f), 15.f);
    float e = __expf(2.f * xc);
    return __fdividef(e - 1.f, e + 1.f);
}
__device__ __forceinline__ float ftanh_fast(float x) {
    float y;
    asm("tanh.approx.f32 %0, %1;" : "=f"(y) : "f"(x));
    return y;
}
__device__ __forceinline__ float fsig(float x) {
    return __fdividef(1.f, 1.f + __expf(-x));
}
__device__ __forceinline__ void mma_bf16(float* d, const unsigned* a4, const unsigned* b2) {
    asm volatile(
        "mma.sync.aligned.m16n8k16.row.col.f32.bf16.bf16.f32 "
        "{%0,%1,%2,%3}, {%4,%5,%6,%7}, {%8,%9}, {%0,%1,%2,%3};\n"
        : "+f"(d[0]), "+f"(d[1]), "+f"(d[2]), "+f"(d[3])
        : "r"(a4[0]), "r"(a4[1]), "r"(a4[2]), "r"(a4[3]), "r"(b2[0]), "r"(b2[1]));
}
__device__ __forceinline__ void lse_upd(float& m, float& s, float v) {
    if (v > m) { s = s * __expf(m - v) + 1.f; m = v; }
    else       { s += __expf(v - m); }
}
__device__ __forceinline__ void lse_comb(float& m, float& s, float m2, float s2) {
    float M = fmaxf(m, m2);
    s = s * __expf(m - M) + s2 * __expf(m2 - M);
    m = M;
}

// ---------------- block reductions (fixed order) ------------------------------
__device__ __forceinline__ float blockReduceSum(float v, float* red) {
    #pragma unroll
    for (int o = 16; o; o >>= 1) v += __shfl_xor_sync(0xffffffffu, v, o);
    if ((threadIdx.x & 31) == 0) red[threadIdx.x >> 5] = v;
    __syncthreads();
    float t = 0.f;
    int nw = blockDim.x >> 5;
    for (int i = 0; i < nw; i++) t += red[i];
    __syncthreads();
    return t;
}
__device__ __forceinline__ float blockReduceMax(float v, float* red) {
    #pragma unroll
    for (int o = 16; o; o >>= 1) v = fmaxf(v, __shfl_xor_sync(0xffffffffu, v, o));
    if ((threadIdx.x & 31) == 0) red[threadIdx.x >> 5] = v;
    __syncthreads();
    float t = red[0];
    int nw = blockDim.x >> 5;
    for (int i = 1; i < nw; i++) t = fmaxf(t, red[i]);
    __syncthreads();
    return t;
}

// ---------------- one-time prep kernels ---------------------------------------
__global__ void k_transpose_bf16(const float* __restrict__ in, __nv_bfloat16* __restrict__ out, int R, int Ccols) {
    __shared__ float t[32][33];
    int c0 = blockIdx.x * 32, r0 = blockIdx.y * 32;
    #pragma unroll
    for (int i = 0; i < 4; i++)
        t[threadIdx.y + i * 8][threadIdx.x] = in[(size_t)(r0 + threadIdx.y + i * 8) * Ccols + c0 + threadIdx.x];
    __syncthreads();
    #pragma unroll
    for (int i = 0; i < 4; i++)
        out[(size_t)(c0 + threadIdx.y + i * 8) * R + r0 + threadIdx.x] =
            __float2bfloat16_rn(t[threadIdx.x][threadIdx.y + i * 8]);
}
__global__ void k_cvt_bf16(const float* __restrict__ in, __nv_bfloat16* __restrict__ out) {
    size_t i = ((size_t)blockIdx.x * 256 + threadIdx.x) * 4;
    float4 v = *(const float4*)&in[i];
    __nv_bfloat162* o = (__nv_bfloat162*)&out[i];
    o[0] = __floats2bfloat162_rn(v.x, v.y);
    o[1] = __floats2bfloat162_rn(v.z, v.w);
}
__global__ void k_zero_h() { g_h[blockIdx.x * 256 + threadIdx.x] = 0.f; }

// ============ BF16 NT GEMM, 128x128 tile, bf16 out (ctx_proj) =================
__global__ __launch_bounds__(256) void gemm_bf16_m128(
    const __nv_bfloat16* __restrict__ A, const __nv_bfloat16* __restrict__ B,
    __nv_bfloat16* __restrict__ C, int N, int K) {
    __shared__ __nv_bfloat16 As[128][72];
    __shared__ __nv_bfloat16 Bs[128][72];
    const int row0 = blockIdx.y * 128, col0 = blockIdx.x * 128;
    const int tid = threadIdx.x;
    const int wid = tid >> 5, lane = tid & 31;
    const int gID = lane >> 2, tig = lane & 3;
    const int m0w = (wid >> 2) * 64, n0w = (wid & 3) * 32;
    const int lrow = tid >> 1, lcol = (tid & 1) * 32;
    float acc[4][4][4] = {};
    for (int k0 = 0; k0 < K; k0 += 64) {
        #pragma unroll
        for (int i = 0; i < 4; i++) {
            *(uint4*)&As[lrow][lcol + i * 8] = *(const uint4*)&A[(size_t)(row0 + lrow) * K + k0 + lcol + i * 8];
            *(uint4*)&Bs[lrow][lcol + i * 8] = *(const uint4*)&B[(size_t)(col0 + lrow) * K + k0 + lcol + i * 8];
        }
        __syncthreads();
        #pragma unroll
        for (int kk = 0; kk < 4; kk++) {
            const int kb = kk * 16;
            unsigned af[4][4], bf[4][2];
            #pragma unroll
            for (int mi = 0; mi < 4; mi++) {
                int r = m0w + mi * 16 + gID;
                int c = kb + tig * 2;
                af[mi][0] = *(const unsigned*)&As[r][c];
                af[mi][1] = *(const unsigned*)&As[r + 8][c];
                af[mi][2] = *(const unsigned*)&As[r][c + 8];
                af[mi][3] = *(const unsigned*)&As[r + 8][c + 8];
            }
            #pragma unroll
            for (int ni = 0; ni < 4; ni++) {
                int n = n0w + ni * 8 + gID;
                int c = kb + tig * 2;
                bf[ni][0] = *(const unsigned*)&Bs[n][c];
                bf[ni][1] = *(const unsigned*)&Bs[n][c + 8];
            }
            #pragma unroll
            for (int mi = 0; mi < 4; mi++)
                #pragma unroll
                for (int ni = 0; ni < 4; ni++)
                    mma_bf16(acc[mi][ni], af[mi], bf[ni]);
        }
        __syncthreads();
    }
    #pragma unroll
    for (int mi = 0; mi < 4; mi++)
        #pragma unroll
        for (int ni = 0; ni < 4; ni++) {
            int r = row0 + m0w + mi * 16 + gID;
            int c = col0 + n0w + ni * 8 + tig * 2;
            *(__nv_bfloat162*)&C[(size_t)r * N + c]       = __floats2bfloat162_rn(acc[mi][ni][0], acc[mi][ni][1]);
            *(__nv_bfloat162*)&C[(size_t)(r + 8) * N + c] = __floats2bfloat162_rn(acc[mi][ni][2], acc[mi][ni][3]);
        }
}

// ============ BF16 NT GEMM, M=64, split-K, dual problem =======================
// A fp32 (converted during smem fill), B bf16 (pre-converted weights).
// Partial C (fp32) at C + blockIdx.z*64*N.
__global__ __launch_bounds__(256) void gemm_bf16_m64_sk(
    const float* __restrict__ A0, const __nv_bfloat16* __restrict__ B0, float* __restrict__ C0,
    const float* __restrict__ A1, const __nv_bfloat16* __restrict__ B1, float* __restrict__ C1,
    int N, int K, int kChunk) {
    const float* A = A0; const __nv_bfloat16* B = B0; float* C = C0;
    if (blockIdx.y == 1) { A = A1; B = B1; C = C1; }
    __shared__ __nv_bfloat16 As[64][72];
    __shared__ __nv_bfloat16 Bs[64][72];
    const int col0 = blockIdx.x * 64;
    const int kbase = blockIdx.z * kChunk;
    const int tid = threadIdx.x;
    const int wid = tid >> 5, lane = tid & 31;
    const int gID = lane >> 2, tig = lane & 3;
    const int lrow = tid >> 2, lseg = (tid & 3) * 16;
    float acc[4][4] = {};
    for (int kt = 0; kt < kChunk; kt += 64) {
        const int k0 = kbase + kt;
        #pragma unroll
        for (int i = 0; i < 4; i++) {
            float4 a = *(const float4*)&A[(size_t)lrow * K + k0 + lseg + i * 4];
            __nv_bfloat162* d = (__nv_bfloat162*)&As[lrow][lseg + i * 4];
            d[0] = __floats2bfloat162_rn(a.x, a.y);
            d[1] = __floats2bfloat162_rn(a.z, a.w);
        }
        *(uint4*)&Bs[lrow][lseg]     = *(const uint4*)&B[(size_t)(col0 + lrow) * K + k0 + lseg];
        *(uint4*)&Bs[lrow][lseg + 8] = *(const uint4*)&B[(size_t)(col0 + lrow) * K + k0 + lseg + 8];
        __syncthreads();
        #pragma unroll
        for (int kk = 0; kk < 4; kk++) {
            const int c = kk * 16 + tig * 2;
            const int n = wid * 8 + gID;
            unsigned bfv[2];
            bfv[0] = *(const unsigned*)&Bs[n][c];
            bfv[1] = *(const unsigned*)&Bs[n][c + 8];
            #pragma unroll
            for (int mi = 0; mi < 4; mi++) {
                int r = mi * 16 + gID;
                unsigned af[4];
                af[0] = *(const unsigned*)&As[r][c];
                af[1] = *(const unsigned*)&As[r + 8][c];
                af[2] = *(const unsigned*)&As[r][c + 8];
                af[3] = *(const unsigned*)&As[r + 8][c + 8];
                mma_bf16(acc[mi], af, bfv);
            }
        }
        __syncthreads();
    }
    float* Cp = C + (size_t)blockIdx.z * 64 * N;
    #pragma unroll
    for (int mi = 0; mi < 4; mi++) {
        int r = mi * 16 + gID;
        int c = col0 + wid * 8 + tig * 2;
        *(float2*)&Cp[(size_t)r * N + c]       = make_float2(acc[mi][0], acc[mi][1]);
        *(float2*)&Cp[(size_t)(r + 8) * N + c] = make_float2(acc[mi][2], acc[mi][3]);
    }
}

// ============ merged GRU GEMMs (bf16): y=0 -> gi (A gathered), y=1 -> gh ======
__global__ __launch_bounds__(256) void gemm_bf16_gigh_sk(
    const float* __restrict__ embW, const int* __restrict__ y, int t,
    const __nv_bfloat16* __restrict__ Wih, float* __restrict__ Cgi,
    const __nv_bfloat16* __restrict__ Whh, float* __restrict__ Cgh) {
    const bool is_gi = (blockIdx.y == 0);
    const int K      = is_gi ? (Edim + Cdim) : Hdim;
    const int kChunk = is_gi ? ((Edim + Cdim) / 4) : (Hdim / 4);
    const __nv_bfloat16* B = is_gi ? Wih : Whh;
    float* C = is_gi ? Cgi : Cgh;
    const int N = 3 * Hdim;
    __shared__ __nv_bfloat16 As[64][72];
    __shared__ __nv_bfloat16 Bs[64][72];
    const int col0 = blockIdx.x * 64;
    const int kbase = blockIdx.z * kChunk;
    const int tid = threadIdx.x;
    const int wid = tid >> 5, lane = tid & 31;
    const int gID = lane >> 2, tig = lane & 3;
    const int lrow = tid >> 2, lseg = (tid & 3) * 16;
    const int yid = is_gi ? y[t * Bn + lrow] : 0;
    float acc[4][4] = {};
    for (int kt = 0; kt < kChunk; kt += 64) {
        const int k0 = kbase + kt;
        const float* Arow;
        if (is_gi) Arow = (k0 < Edim) ? &embW[(size_t)yid * Edim + k0]
                                      : &g_z[lrow * Cdim + (k0 - Edim)];
        else       Arow = &g_h[lrow * Hdim + k0];
        #pragma unroll
        for (int i = 0; i < 4; i++) {
            float4 a = *(const float4*)&Arow[lseg + i * 4];
            __nv_bfloat162* d = (__nv_bfloat162*)&As[lrow][lseg + i * 4];
            d[0] = __floats2bfloat162_rn(a.x, a.y);
            d[1] = __floats2bfloat162_rn(a.z, a.w);
        }
        *(uint4*)&Bs[lrow][lseg]     = *(const uint4*)&B[(size_t)(col0 + lrow) * K + k0 + lseg];
        *(uint4*)&Bs[lrow][lseg + 8] = *(const uint4*)&B[(size_t)(col0 + lrow) * K + k0 + lseg + 8];
        __syncthreads();
        #pragma unroll
        for (int kk = 0; kk < 4; kk++) {
            const int c = kk * 16 + tig * 2;
            const int n = wid * 8 + gID;
            unsigned bfv[2];
            bfv[0] = *(const unsigned*)&Bs[n][c];
            bfv[1] = *(const unsigned*)&Bs[n][c + 8];
            #pragma unroll
            for (int mi = 0; mi < 4; mi++) {
                int r = mi * 16 + gID;
                unsigned af[4];
                af[0] = *(const unsigned*)&As[r][c];
                af[1] = *(const unsigned*)&As[r + 8][c];
                af[2] = *(const unsigned*)&As[r][c + 8];
                af[3] = *(const unsigned*)&As[r + 8][c + 8];
                mma_bf16(acc[mi], af, bfv);
            }
        }
        __syncthreads();
    }
    float* Cp = C + (size_t)blockIdx.z * 64 * N;
    #pragma unroll
    for (int mi = 0; mi < 4; mi++) {
        int r = mi * 16 + gID;
        int c = col0 + wid * 8 + tig * 2;
        *(float2*)&Cp[(size_t)r * N + c]       = make_float2(acc[mi][0], acc[mi][1]);
        *(float2*)&Cp[(size_t)(r + 8) * N + c] = make_float2(acc[mi][2], acc[mi][3]);
    }
}

// ============ BF16 logits GEMM + fused partial NLL ============================
__global__ __launch_bounds__(256) void gemm_bf16_logits_nll(
    const __nv_bfloat16* __restrict__ A, const __nv_bfloat16* __restrict__ B,
    const float* __restrict__ bias, const int* __restrict__ y, int t, int K) {
    __shared__ __align__(16) unsigned char sbuf[9216 + 36864];
    __nv_bfloat16 (*As)[72] = reinterpret_cast<__nv_bfloat16(*)[72]>(sbuf);
    __nv_bfloat16 (*Bs)[72] = reinterpret_cast<__nv_bfloat16(*)[72]>(sbuf + 9216);
    float (*sm)[8] = reinterpret_cast<float(*)[8]>(sbuf);           // overlays As
    float (*ss)[8] = reinterpret_cast<float(*)[8]>(sbuf + 2048);    // overlays As
    const int col0 = blockIdx.x * 256;
    const int tid = threadIdx.x;
    const int wid = tid >> 5, lane = tid & 31;
    const int gID = lane >> 2, tig = lane & 3;
    const int n0w = wid * 32;
    float acc[4][4][4] = {};
    for (int k0 = 0; k0 < K; k0 += 64) {
        {
            int ar = tid >> 2, as = (tid & 3) * 16;
            *(uint4*)&As[ar][as]     = *(const uint4*)&A[(size_t)ar * K + k0 + as];
            *(uint4*)&As[ar][as + 8] = *(const uint4*)&A[(size_t)ar * K + k0 + as + 8];
            #pragma unroll
            for (int i = 0; i < 8; i++)
                *(uint4*)&Bs[tid][i * 8] = *(const uint4*)&B[(size_t)(col0 + tid) * K + k0 + i * 8];
        }
        __syncthreads();
        #pragma unroll
        for (int kk = 0; kk < 4; kk++) {
            const int kb = kk * 16;
            unsigned af[4][4], bf[4][2];
            #pragma unroll
            for (int mi = 0; mi < 4; mi++) {
                int r = mi * 16 + gID;
                int c = kb + tig * 2;
                af[mi][0] = *(const unsigned*)&As[r][c];
                af[mi][1] = *(const unsigned*)&As[r + 8][c];
                af[mi][2] = *(const unsigned*)&As[r][c + 8];
                af[mi][3] = *(const unsigned*)&As[r + 8][c + 8];
            }
            #pragma unroll
            for (int ni = 0; ni < 4; ni++) {
                int n = n0w + ni * 8 + gID;
                int c = kb + tig * 2;
                bf[ni][0] = *(const unsigned*)&Bs[n][c];
                bf[ni][1] = *(const unsigned*)&Bs[n][c + 8];
            }
            #pragma unroll
            for (int mi = 0; mi < 4; mi++)
                #pragma unroll
                for (int ni = 0; ni < 4; ni++)
                    mma_bf16(acc[mi][ni], af[mi], bf[ni]);
        }
        __syncthreads();
    }
    #pragma unroll
    for (int mi = 0; mi < 4; mi++) {
        const int r  = mi * 16 + gID;
        const int r2 = r + 8;
        const int tgt  = y[(t + 1) * Bn + r];
        const int tgt2 = y[(t + 1) * Bn + r2];
        float m1 = -1e30f, s1 = 0.f, m2 = -1e30f, s2 = 0.f;
        #pragma unroll
        for (int ni = 0; ni < 4; ni++) {
            int c = col0 + n0w + ni * 8 + tig * 2;
            float b0 = bias[c], b1 = bias[c + 1];
            float v0 = acc[mi][ni][0] + b0, v1 = acc[mi][ni][1] + b1;
            float v2 = acc[mi][ni][2] + b0, v3 = acc[mi][ni][3] + b1;
            if (c == tgt)      g_ltgt[r]  = v0;
            if (c + 1 == tgt)  g_ltgt[r]  = v1;
            if (c == tgt2)     g_ltgt[r2] = v2;
            if (c + 1 == tgt2) g_ltgt[r2] = v3;
            lse_upd(m1, s1, v0); lse_upd(m1, s1, v1);
            lse_upd(m2, s2, v2); lse_upd(m2, s2, v3);
        }
        #pragma unroll
        for (int off = 1; off <= 2; off <<= 1) {
            float om = __shfl_xor_sync(0xffffffffu, m1, off);
            float os = __shfl_xor_sync(0xffffffffu, s1, off);
            lse_comb(m1, s1, om, os);
            om = __shfl_xor_sync(0xffffffffu, m2, off);
            os = __shfl_xor_sync(0xffffffffu, s2, off);
            lse_comb(m2, s2, om, os);
        }
        if (tig == 0) {
            sm[r][wid] = m1; ss[r][wid] = s1;
            sm[r2][wid] = m2; ss[r2][wid] = s2;
        }
    }
    __syncthreads();
    if (tid < 64) {
        float M = sm[tid][0], S = ss[tid][0];
        #pragma unroll
        for (int w = 1; w < 8; w++) lse_comb(M, S, sm[tid][w], ss[tid][w]);
        g_pm[blockIdx.x * Bn + tid] = M;
        g_ps[blockIdx.x * Bn + tid] = S;
    }
}

// ============ fused attention + previous step's NLL finalize ==================
// warp 7 reduces the NVBLK (m,s) partials of step t-1 (if t>0) while the other
// warps proceed with attention work; g_pm/g_ps/g_ltgt for step t-1 are not
// overwritten until later this step (logits_nll runs after k_att).
__global__ __launch_bounds__(256) void k_att(const float* __restrict__ mlp,
                                             const int* __restrict__ y, int t) {
    const int b = blockIdx.x;
    const int tid = threadIdx.x;
    const int wid = tid >> 5, lane = tid & 31;
    __shared__ float sc[200];
    __shared__ float red[8];
    if (t > 0 && wid == 7) {
        float m = -1e30f, s = 0.f;
        for (int i = lane; i < NVBLK; i += 32)
            lse_comb(m, s, g_pm[i * Bn + b], g_ps[i * Bn + b]);
        #pragma unroll
        for (int off = 16; off; off >>= 1) {
            float om = __shfl_xor_sync(0xffffffffu, m, off);
            float os = __shfl_xor_sync(0xffffffffu, s, off);
            lse_comb(m, s, om, os);
        }
        if (lane == 0) {
            int tgt = y[t * Bn + b];   // target of step t-1 is y[(t-1)+1]
            g_nll[(t - 1) * Bn + b] = (tgt != 0) ? (m + logf(s) - g_ltgt[b]) : 0.f;
        }
    }
    float hqv[32], mlpv[32];
    #pragma unroll
    for (int j = 0; j < 4; j++) {
        #pragma unroll
        for (int u = 0; u < 8; u++) {
            int m = lane * 8 + j * 256 + u;
            float v = g_hq_part[b * Cdim + m]
                    + g_hq_part[(Bn + b) * Cdim + m]
                    + g_hq_part[(2 * Bn + b) * Cdim + m]
                    + g_hq_part[(3 * Bn + b) * Cdim + m];
            hqv[j * 8 + u] = v;
            mlpv[j * 8 + u] = mlp[m];
        }
    }
    for (int s = wid; s < Sdim; s += 8) {
        const __nv_bfloat16* row = g_ctxp_bf16 + ((size_t)s * Bn + b) * Cdim;
        float sum = 0.f;
        #pragma unroll
        for (int j = 0; j < 4; j++) {
            int m = lane * 8 + j * 256;
            uint4 u = *(const uint4*)&row[m];
            float2 f0 = __bfloat1622float2(*(__nv_bfloat162*)&u.x);
            float2 f1 = __bfloat1622float2(*(__nv_bfloat162*)&u.y);
            float2 f2 = __bfloat1622float2(*(__nv_bfloat162*)&u.z);
            float2 f3 = __bfloat1622float2(*(__nv_bfloat162*)&u.w);
            sum += ftanh_fast(f0.x + hqv[j * 8 + 0]) * mlpv[j * 8 + 0];
            sum += ftanh_fast(f0.y + hqv[j * 8 + 1]) * mlpv[j * 8 + 1];
            sum += ftanh_fast(f1.x + hqv[j * 8 + 2]) * mlpv[j * 8 + 2];
            sum += ftanh_fast(f1.y + hqv[j * 8 + 3]) * mlpv[j * 8 + 3];
            sum += ftanh_fast(f2.x + hqv[j * 8 + 4]) * mlpv[j * 8 + 4];
            sum += ftanh_fast(f2.y + hqv[j * 8 + 5]) * mlpv[j * 8 + 5];
            sum += ftanh_fast(f3.x + hqv[j * 8 + 6]) * mlpv[j * 8 + 6];
            sum += ftanh_fast(f3.y + hqv[j * 8 + 7]) * mlpv[j * 8 + 7];
        }
        #pragma unroll
        for (int o = 16; o; o >>= 1) sum += __shfl_xor_sync(0xffffffffu, sum, o);
        if (lane == 0) sc[s] = sum;
    }
    __syncthreads();
    float v = (tid < Sdim) ? sc[tid] : -1e30f;
    float mx = blockReduceMax(v, red);
    float e = (tid < Sdim) ? __expf(v - mx) : 0.f;
    float tot = blockReduceSum(e, red);
    if (tid < Sdim) sc[tid] = __fdividef(e, tot);
    __syncthreads();
    const int c4 = tid * 4;
    float4 acc = make_float4(0.f, 0.f, 0.f, 0.f);
    #pragma unroll 4
    for (int s = 0; s < Sdim; s++) {
        float a = sc[s];
        uint2 u = *(const uint2*)&g_ctx_bf16[((size_t)s * Bn + b) * Cdim + c4];
        float2 f0 = __bfloat1622float2(*(__nv_bfloat162*)&u.x);
        float2 f1 = __bfloat1622float2(*(__nv_bfloat162*)&u.y);
        acc.x = fmaf(a, f0.x, acc.x); acc.y = fmaf(a, f0.y, acc.y);
        acc.z = fmaf(a, f1.x, acc.z); acc.w = fmaf(a, f1.y, acc.w);
    }
    *(float4*)&g_z[b * Cdim + c4] = acc;
}

// ---------------- per-step elementwise kernels --------------------------------
__global__ void k_gru(const float* __restrict__ b_ih, const float* __restrict__ b_hh) {
    const int i = blockIdx.x * 256 + threadIdx.x;
    const int b = i >> 10, j = i & (Hdim - 1);
    float ir = b_ih[j], iz = b_ih[Hdim + j], in_ = b_ih[2 * Hdim + j];
    #pragma unroll
    for (int p = 0; p < 4; p++) {
        const float* g = g_gi_part + ((size_t)p * Bn + b) * 3 * Hdim;
        ir += g[j]; iz += g[Hdim + j]; in_ += g[2 * Hdim + j];
    }
    float hr = b_hh[j], hz = b_hh[Hdim + j], hn = b_hh[2 * Hdim + j];
    #pragma unroll
    for (int p = 0; p < 4; p++) {
        const float* g = g_gh_part + ((size_t)p * Bn + b) * 3 * Hdim;
        hr += g[j]; hz += g[Hdim + j]; hn += g[2 * Hdim + j];
    }
    float r = fsig(ir + hr);
    float zz = fsig(iz + hz);
    float n = ftanh(in_ + r * hn);
    float hold = g_h[i];
    g_h[i] = (1.f - zz) * n + zz * hold;
}

__global__ void k_pvec(const float* __restrict__ embW, const int* __restrict__ y,
                       const float* __restrict__ h2o_b, const float* __restrict__ octx_b, int t) {
    const int i = blockIdx.x * 256 + threadIdx.x;
    const int b = i >> 9, e = i & (Edim - 1);
    float o1 = h2o_b[e], o2 = octx_b[e];
    #pragma unroll
    for (int p = 0; p < 4; p++) {
        o1 += g_o1_part[p * Bn * Edim + i];
        o2 += g_o2_part[p * Bn * Edim + i];
    }
    float l = ftanh(o1);
    l += embW[(size_t)y[t * Bn + b] * Edim + e];
    l += o2;
    g_p_bf16[i] = __float2bfloat16_rn(ftanh(l));
}

// final: last step's NLL from partials + total sum
__global__ __launch_bounds__(256) void k_final(const int* __restrict__ y, float* __restrict__ out) {
    __shared__ float red[8];
    const int tid = threadIdx.x;
    if (tid < Bn) {
        float m = -1e30f, s = 0.f;
        for (int i = 0; i < NVBLK; i++)
            lse_comb(m, s, g_pm[i * Bn + tid], g_ps[i * Bn + tid]);
        int tgt = y[NSTEP * Bn + tid];
        g_nll[(NSTEP - 1) * Bn + tid] = (tgt != 0) ? (m + logf(s) - g_ltgt[tid]) : 0.f;
    }
    __syncthreads();
    float s = 0.f;
    for (int i = tid; i < NSTEP * Bn; i += 256) s += g_nll[i];
    float tot = blockReduceSum(s, red);
    if (tid == 0) out[0] = tot;
}

// ---------------- launch ------------------------------------------------------
extern "C" void kernel_launch(void* const* d_in, const int* in_sizes, int n_in,
                              void* d_out, int out_size) {
    const float* ctx         = (const float*)d_in[0];
    const int*   y           = (const int*)  d_in[1];
    const float* embW        = (const float*)d_in[2];
    const float* att_ctx2ctx = (const float*)d_in[3];
    const float* att_hid2ctx = (const float*)d_in[4];
    const float* att_mlp     = (const float*)d_in[5];
    const float* gru_W_ih    = (const float*)d_in[6];
    const float* gru_b_ih    = (const float*)d_in[7];
    const float* gru_W_hh    = (const float*)d_in[8];
    const float* gru_b_hh    = (const float*)d_in[9];
    const float* h2o_W       = (const float*)d_in[10];
    const float* h2o_b       = (const float*)d_in[11];
    const float* octx_W      = (const float*)d_in[12];
    const float* octx_b      = (const float*)d_in[13];
    const float* o2p_W       = (const float*)d_in[14];
    const float* o2p_b       = (const float*)d_in[15];

    float *p_h, *p_hqp, *p_z, *p_gip, *p_ghp, *p_o1p, *p_o2p;
    __nv_bfloat16 *p_ctxpbf, *p_ctxbf, *p_WctxTbf, *p_WhidTbf, *p_Wihbf, *p_Whhbf,
                  *p_h2obf, *p_octxbf, *p_Wbf, *p_pbf;
    cudaGetSymbolAddress((void**)&p_ctxpbf,  g_ctxp_bf16);
    cudaGetSymbolAddress((void**)&p_ctxbf,   g_ctx_bf16);
    cudaGetSymbolAddress((void**)&p_WctxTbf, g_WctxT_bf16);
    cudaGetSymbolAddress((void**)&p_WhidTbf, g_WhidT_bf16);
    cudaGetSymbolAddress((void**)&p_Wihbf,   g_Wih_bf16);
    cudaGetSymbolAddress((void**)&p_Whhbf,   g_Whh_bf16);
    cudaGetSymbolAddress((void**)&p_h2obf,   g_h2o_bf16);
    cudaGetSymbolAddress((void**)&p_octxbf,  g_octx_bf16);
    cudaGetSymbolAddress((void**)&p_Wbf,     g_Wo2p_bf16);
    cudaGetSymbolAddress((void**)&p_pbf,     g_p_bf16);
    cudaGetSymbolAddress((void**)&p_h,       g_h);
    cudaGetSymbolAddress((void**)&p_hqp,     g_hq_part);
    cudaGetSymbolAddress((void**)&p_z,       g_z);
    cudaGetSymbolAddress((void**)&p_gip,     g_gi_part);
    cudaGetSymbolAddress((void**)&p_ghp,     g_gh_part);
    cudaGetSymbolAddress((void**)&p_o1p,     g_o1_part);
    cudaGetSymbolAddress((void**)&p_o2p,     g_o2_part);

    // one-time prep
    k_cvt_bf16<<<((size_t)Sdim * Bn * Cdim) / 1024, 256>>>(ctx, p_ctxbf);
    k_transpose_bf16<<<dim3(32, 32), dim3(32, 8)>>>(att_ctx2ctx, p_WctxTbf, Cdim, Cdim);
    k_transpose_bf16<<<dim3(32, 32), dim3(32, 8)>>>(att_hid2ctx, p_WhidTbf, Hdim, Cdim);
    k_cvt_bf16<<<(3 * Hdim * (Edim + Cdim)) / 1024, 256>>>(gru_W_ih, p_Wihbf);
    k_cvt_bf16<<<(3 * Hdim * Hdim) / 1024, 256>>>(gru_W_hh, p_Whhbf);
    k_cvt_bf16<<<(Edim * Hdim) / 1024, 256>>>(h2o_W, p_h2obf);
    k_cvt_bf16<<<(Edim * Cdim) / 1024, 256>>>(octx_W, p_octxbf);
    k_cvt_bf16<<<((size_t)Vdim * Edim) / 1024, 256>>>(o2p_W, p_Wbf);
    k_zero_h<<<(Bn * Hdim) / 256, 256>>>();
    gemm_bf16_m128<<<dim3(Cdim / 128, (Sdim * Bn) / 128), 256>>>(
        p_ctxbf, p_WctxTbf, p_ctxpbf, Cdim, Cdim);

    for (int t = 0; t < NSTEP; t++) {
        gemm_bf16_m64_sk<<<dim3(Cdim / 64, 1, 4), 256>>>(
            p_h, p_WhidTbf, p_hqp, p_h, p_WhidTbf, p_hqp, Cdim, Hdim, Hdim / 4);
        k_att<<<Bn, 256>>>(att_mlp, y, t);
        gemm_bf16_gigh_sk<<<dim3((3 * Hdim) / 64, 2, 4), 256>>>(
            embW, y, t, p_Wihbf, p_gip, p_Whhbf, p_ghp);
        k_gru<<<(Bn * Hdim) / 256, 256>>>(gru_b_ih, gru_b_hh);
        gemm_bf16_m64_sk<<<dim3(Edim / 64, 2, 4), 256>>>(
            p_h, p_h2obf, p_o1p, p_z, p_octxbf, p_o2p, Edim, Hdim, Hdim / 4);
        k_pvec<<<(Bn * Edim) / 256, 256>>>(embW, y, h2o_b, octx_b, t);
        gemm_bf16_logits_nll<<<NVBLK, 256>>>(p_pbf, p_Wbf, o2p_b, y, t, Edim);
    }
    k_final<<<1, 256>>>(y, (float*)d_out);
}

// round 11
// speedup vs baseline: 4.0486x; 1.0489x over previous
#include <cuda_runtime.h>
#include <cuda_bf16.h>
#include <math.h>

#define Sdim 196
#define Bn   64
#define Cdim 1024
#define Hdim 1024
#define Edim 512
#define Vdim 32000
#define NSTEP 19
#define NVBLK (Vdim / 256)   // 125 logits blocks

// ---------------- scratch (device globals) -----------------------------------
__device__ __nv_bfloat16 g_ctxp_bf16[(size_t)Sdim * Bn * Cdim];
__device__ __nv_bfloat16 g_ctx_bf16[(size_t)Sdim * Bn * Cdim];
__device__ __nv_bfloat16 g_WctxT_bf16[Cdim * Cdim];
__device__ __nv_bfloat16 g_WhidT_bf16[Hdim * Cdim];
__device__ __nv_bfloat16 g_Wih_bf16[3 * Hdim * (Edim + Cdim)];
__device__ __nv_bfloat16 g_Whh_bf16[3 * Hdim * Hdim];
__device__ __nv_bfloat16 g_h2o_bf16[Edim * Hdim];
__device__ __nv_bfloat16 g_octx_bf16[Edim * Cdim];
__device__ __nv_bfloat16 g_Wo2p_bf16[(size_t)Vdim * Edim];
__device__ __nv_bfloat16 g_p_bf16[Bn * Edim];
__device__ float g_h[Bn * Hdim];
__device__ float g_hq_part[4 * Bn * Cdim];
__device__ float g_z[Bn * Cdim];
__device__ float g_gi_part[4 * Bn * 3 * Hdim];
__device__ float g_gh_part[4 * Bn * 3 * Hdim];
__device__ float g_o1_part[4 * Bn * Edim];
__device__ float g_o2_part[4 * Bn * Edim];
__device__ float g_pm[NVBLK * Bn];
__device__ float g_ps[NVBLK * Bn];
__device__ float g_ltgt[Bn];
__device__ float g_nll[NSTEP * Bn];

// ---------------- fast math ---------------------------------------------------
__device__ __forceinline__ float ftanh(float x) {
    float xc = fminf(fmaxf(x, -15.f), 15.f);
    float e = __expf(2.f * xc);
    return __fdividef(e - 1.f, e + 1.f);
}
__device__ __forceinline__ float ftanh_fast(float x) {
    float y;
    asm("tanh.approx.f32 %0, %1;" : "=f"(y) : "f"(x));
    return y;
}
__device__ __forceinline__ float fsig(float x) {
    return __fdividef(1.f, 1.f + __expf(-x));
}
__device__ __forceinline__ void mma_bf16(float* d, const unsigned* a4, const unsigned* b2) {
    asm volatile(
        "mma.sync.aligned.m16n8k16.row.col.f32.bf16.bf16.f32 "
        "{%0,%1,%2,%3}, {%4,%5,%6,%7}, {%8,%9}, {%0,%1,%2,%3};\n"
        : "+f"(d[0]), "+f"(d[1]), "+f"(d[2]), "+f"(d[3])
        : "r"(a4[0]), "r"(a4[1]), "r"(a4[2]), "r"(a4[3]), "r"(b2[0]), "r"(b2[1]));
}
__device__ __forceinline__ void lse_upd(float& m, float& s, float v) {
    if (v > m) { s = s * __expf(m - v) + 1.f; m = v; }
    else       { s += __expf(v - m); }
}
__device__ __forceinline__ void lse_comb(float& m, float& s, float m2, float s2) {
    float M = fmaxf(m, m2);
    s = s * __expf(m - M) + s2 * __expf(m2 - M);
    m = M;
}

// ---------------- block reductions (fixed order) ------------------------------
__device__ __forceinline__ float blockReduceSum(float v, float* red) {
    #pragma unroll
    for (int o = 16; o; o >>= 1) v += __shfl_xor_sync(0xffffffffu, v, o);
    if ((threadIdx.x & 31) == 0) red[threadIdx.x >> 5] = v;
    __syncthreads();
    float t = 0.f;
    int nw = blockDim.x >> 5;
    for (int i = 0; i < nw; i++) t += red[i];
    __syncthreads();
    return t;
}
__device__ __forceinline__ float blockReduceMax(float v, float* red) {
    #pragma unroll
    for (int o = 16; o; o >>= 1) v = fmaxf(v, __shfl_xor_sync(0xffffffffu, v, o));
    if ((threadIdx.x & 31) == 0) red[threadIdx.x >> 5] = v;
    __syncthreads();
    float t = red[0];
    int nw = blockDim.x >> 5;
    for (int i = 1; i < nw; i++) t = fmaxf(t, red[i]);
    __syncthreads();
    return t;
}

// ---------------- one-time prep kernels ---------------------------------------
__global__ void k_transpose_bf16(const float* __restrict__ in, __nv_bfloat16* __restrict__ out, int R, int Ccols) {
    __shared__ float t[32][33];
    int c0 = blockIdx.x * 32, r0 = blockIdx.y * 32;
    #pragma unroll
    for (int i = 0; i < 4; i++)
        t[threadIdx.y + i * 8][threadIdx.x] = in[(size_t)(r0 + threadIdx.y + i * 8) * Ccols + c0 + threadIdx.x];
    __syncthreads();
    #pragma unroll
    for (int i = 0; i < 4; i++)
        out[(size_t)(c0 + threadIdx.y + i * 8) * R + r0 + threadIdx.x] =
            __float2bfloat16_rn(t[threadIdx.x][threadIdx.y + i * 8]);
}

// all plain fp32->bf16 conversions in one launch (segmented by float4 index)
#define CVT_N0 ((size_t)Sdim * Bn * Cdim / 4)
#define CVT_N1 (CVT_N0 + (size_t)3 * Hdim * (Edim + Cdim) / 4)
#define CVT_N2 (CVT_N1 + (size_t)3 * Hdim * Hdim / 4)
#define CVT_N3 (CVT_N2 + (size_t)Edim * Hdim / 4)
#define CVT_N4 (CVT_N3 + (size_t)Edim * Cdim / 4)
#define CVT_N5 (CVT_N4 + (size_t)Vdim * Edim / 4)
__global__ void k_cvt_all(const float* __restrict__ ctx, const float* __restrict__ Wih,
                          const float* __restrict__ Whh, const float* __restrict__ h2o,
                          const float* __restrict__ octx, const float* __restrict__ o2p) {
    size_t i = (size_t)blockIdx.x * 256 + threadIdx.x;   // float4 index
    const float* src; __nv_bfloat16* dst; size_t off;
    if      (i < CVT_N0) { src = ctx;  dst = g_ctx_bf16;  off = i; }
    else if (i < CVT_N1) { src = Wih;  dst = g_Wih_bf16;  off = i - CVT_N0; }
    else if (i < CVT_N2) { src = Whh;  dst = g_Whh_bf16;  off = i - CVT_N1; }
    else if (i < CVT_N3) { src = h2o;  dst = g_h2o_bf16;  off = i - CVT_N2; }
    else if (i < CVT_N4) { src = octx; dst = g_octx_bf16; off = i - CVT_N3; }
    else if (i < CVT_N5) { src = o2p;  dst = g_Wo2p_bf16; off = i - CVT_N4; }
    else return;
    float4 v = *(const float4*)&src[off * 4];
    __nv_bfloat162* o = (__nv_bfloat162*)&dst[off * 4];
    o[0] = __floats2bfloat162_rn(v.x, v.y);
    o[1] = __floats2bfloat162_rn(v.z, v.w);
}

// zero h (64K floats) and hq_part (256K floats): h0 = 0 => hq0 = 0
__global__ void k_zero_init() {
    int i = blockIdx.x * 256 + threadIdx.x;
    if (i < Bn * Hdim) g_h[i] = 0.f;
    else g_hq_part[i - Bn * Hdim] = 0.f;
}

// ============ BF16 NT GEMM, 128x128 tile, bf16 out (ctx_proj) =================
__global__ __launch_bounds__(256) void gemm_bf16_m128(
    const __nv_bfloat16* __restrict__ A, const __nv_bfloat16* __restrict__ B,
    __nv_bfloat16* __restrict__ C, int N, int K) {
    __shared__ __nv_bfloat16 As[128][72];
    __shared__ __nv_bfloat16 Bs[128][72];
    const int row0 = blockIdx.y * 128, col0 = blockIdx.x * 128;
    const int tid = threadIdx.x;
    const int wid = tid >> 5, lane = tid & 31;
    const int gID = lane >> 2, tig = lane & 3;
    const int m0w = (wid >> 2) * 64, n0w = (wid & 3) * 32;
    const int lrow = tid >> 1, lcol = (tid & 1) * 32;
    float acc[4][4][4] = {};
    for (int k0 = 0; k0 < K; k0 += 64) {
        #pragma unroll
        for (int i = 0; i < 4; i++) {
            *(uint4*)&As[lrow][lcol + i * 8] = *(const uint4*)&A[(size_t)(row0 + lrow) * K + k0 + lcol + i * 8];
            *(uint4*)&Bs[lrow][lcol + i * 8] = *(const uint4*)&B[(size_t)(col0 + lrow) * K + k0 + lcol + i * 8];
        }
        __syncthreads();
        #pragma unroll
        for (int kk = 0; kk < 4; kk++) {
            const int kb = kk * 16;
            unsigned af[4][4], bf[4][2];
            #pragma unroll
            for (int mi = 0; mi < 4; mi++) {
                int r = m0w + mi * 16 + gID;
                int c = kb + tig * 2;
                af[mi][0] = *(const unsigned*)&As[r][c];
                af[mi][1] = *(const unsigned*)&As[r + 8][c];
                af[mi][2] = *(const unsigned*)&As[r][c + 8];
                af[mi][3] = *(const unsigned*)&As[r + 8][c + 8];
            }
            #pragma unroll
            for (int ni = 0; ni < 4; ni++) {
                int n = n0w + ni * 8 + gID;
                int c = kb + tig * 2;
                bf[ni][0] = *(const unsigned*)&Bs[n][c];
                bf[ni][1] = *(const unsigned*)&Bs[n][c + 8];
            }
            #pragma unroll
            for (int mi = 0; mi < 4; mi++)
                #pragma unroll
                for (int ni = 0; ni < 4; ni++)
                    mma_bf16(acc[mi][ni], af[mi], bf[ni]);
        }
        __syncthreads();
    }
    #pragma unroll
    for (int mi = 0; mi < 4; mi++)
        #pragma unroll
        for (int ni = 0; ni < 4; ni++) {
            int r = row0 + m0w + mi * 16 + gID;
            int c = col0 + n0w + ni * 8 + tig * 2;
            *(__nv_bfloat162*)&C[(size_t)r * N + c]       = __floats2bfloat162_rn(acc[mi][ni][0], acc[mi][ni][1]);
            *(__nv_bfloat162*)&C[(size_t)(r + 8) * N + c] = __floats2bfloat162_rn(acc[mi][ni][2], acc[mi][ni][3]);
        }
}

// ============ BF16 triple GEMM (o1, o2, hq-next), M=64, split-K ===============
// blockIdx.y: 0 -> o1 = h @ h2o^T (N=Edim); 1 -> o2 = z @ octx^T (N=Edim);
//             2 -> hq = h @ WhidT^T (N=Cdim).  All K=Hdim.
__global__ __launch_bounds__(256) void gemm_bf16_m64_tri(
    const float* __restrict__ h, const float* __restrict__ z,
    const __nv_bfloat16* __restrict__ Bh2o, const __nv_bfloat16* __restrict__ Boctx,
    const __nv_bfloat16* __restrict__ Bhid,
    float* __restrict__ Co1, float* __restrict__ Co2, float* __restrict__ Chq) {
    const int prob = blockIdx.y;
    const float* A; const __nv_bfloat16* B; float* C; int N;
    if (prob == 0)      { A = h; B = Bh2o;  C = Co1; N = Edim; }
    else if (prob == 1) { A = z; B = Boctx; C = Co2; N = Edim; }
    else                { A = h; B = Bhid;  C = Chq; N = Cdim; }
    const int col0 = blockIdx.x * 64;
    if (col0 >= N) return;
    const int K = Hdim, kChunk = Hdim / 4;
    __shared__ __nv_bfloat16 As[64][72];
    __shared__ __nv_bfloat16 Bs[64][72];
    const int kbase = blockIdx.z * kChunk;
    const int tid = threadIdx.x;
    const int wid = tid >> 5, lane = tid & 31;
    const int gID = lane >> 2, tig = lane & 3;
    const int lrow = tid >> 2, lseg = (tid & 3) * 16;
    float acc[4][4] = {};
    for (int kt = 0; kt < kChunk; kt += 64) {
        const int k0 = kbase + kt;
        #pragma unroll
        for (int i = 0; i < 4; i++) {
            float4 a = *(const float4*)&A[(size_t)lrow * K + k0 + lseg + i * 4];
            __nv_bfloat162* d = (__nv_bfloat162*)&As[lrow][lseg + i * 4];
            d[0] = __floats2bfloat162_rn(a.x, a.y);
            d[1] = __floats2bfloat162_rn(a.z, a.w);
        }
        *(uint4*)&Bs[lrow][lseg]     = *(const uint4*)&B[(size_t)(col0 + lrow) * K + k0 + lseg];
        *(uint4*)&Bs[lrow][lseg + 8] = *(const uint4*)&B[(size_t)(col0 + lrow) * K + k0 + lseg + 8];
        __syncthreads();
        #pragma unroll
        for (int kk = 0; kk < 4; kk++) {
            const int c = kk * 16 + tig * 2;
            const int n = wid * 8 + gID;
            unsigned bfv[2];
            bfv[0] = *(const unsigned*)&Bs[n][c];
            bfv[1] = *(const unsigned*)&Bs[n][c + 8];
            #pragma unroll
            for (int mi = 0; mi < 4; mi++) {
                int r = mi * 16 + gID;
                unsigned af[4];
                af[0] = *(const unsigned*)&As[r][c];
                af[1] = *(const unsigned*)&As[r + 8][c];
                af[2] = *(const unsigned*)&As[r][c + 8];
                af[3] = *(const unsigned*)&As[r + 8][c + 8];
                mma_bf16(acc[mi], af, bfv);
            }
        }
        __syncthreads();
    }
    float* Cp = C + (size_t)blockIdx.z * 64 * N;
    #pragma unroll
    for (int mi = 0; mi < 4; mi++) {
        int r = mi * 16 + gID;
        int c = col0 + wid * 8 + tig * 2;
        *(float2*)&Cp[(size_t)r * N + c]       = make_float2(acc[mi][0], acc[mi][1]);
        *(float2*)&Cp[(size_t)(r + 8) * N + c] = make_float2(acc[mi][2], acc[mi][3]);
    }
}

// ============ merged GRU GEMMs (bf16): y=0 -> gi (A gathered), y=1 -> gh ======
__global__ __launch_bounds__(256) void gemm_bf16_gigh_sk(
    const float* __restrict__ embW, const int* __restrict__ y, int t,
    const __nv_bfloat16* __restrict__ Wih, float* __restrict__ Cgi,
    const __nv_bfloat16* __restrict__ Whh, float* __restrict__ Cgh) {
    const bool is_gi = (blockIdx.y == 0);
    const int K      = is_gi ? (Edim + Cdim) : Hdim;
    const int kChunk = is_gi ? ((Edim + Cdim) / 4) : (Hdim / 4);
    const __nv_bfloat16* B = is_gi ? Wih : Whh;
    float* C = is_gi ? Cgi : Cgh;
    const int N = 3 * Hdim;
    __shared__ __nv_bfloat16 As[64][72];
    __shared__ __nv_bfloat16 Bs[64][72];
    const int col0 = blockIdx.x * 64;
    const int kbase = blockIdx.z * kChunk;
    const int tid = threadIdx.x;
    const int wid = tid >> 5, lane = tid & 31;
    const int gID = lane >> 2, tig = lane & 3;
    const int lrow = tid >> 2, lseg = (tid & 3) * 16;
    const int yid = is_gi ? y[t * Bn + lrow] : 0;
    float acc[4][4] = {};
    for (int kt = 0; kt < kChunk; kt += 64) {
        const int k0 = kbase + kt;
        const float* Arow;
        if (is_gi) Arow = (k0 < Edim) ? &embW[(size_t)yid * Edim + k0]
                                      : &g_z[lrow * Cdim + (k0 - Edim)];
        else       Arow = &g_h[lrow * Hdim + k0];
        #pragma unroll
        for (int i = 0; i < 4; i++) {
            float4 a = *(const float4*)&Arow[lseg + i * 4];
            __nv_bfloat162* d = (__nv_bfloat162*)&As[lrow][lseg + i * 4];
            d[0] = __floats2bfloat162_rn(a.x, a.y);
            d[1] = __floats2bfloat162_rn(a.z, a.w);
        }
        *(uint4*)&Bs[lrow][lseg]     = *(const uint4*)&B[(size_t)(col0 + lrow) * K + k0 + lseg];
        *(uint4*)&Bs[lrow][lseg + 8] = *(const uint4*)&B[(size_t)(col0 + lrow) * K + k0 + lseg + 8];
        __syncthreads();
        #pragma unroll
        for (int kk = 0; kk < 4; kk++) {
            const int c = kk * 16 + tig * 2;
            const int n = wid * 8 + gID;
            unsigned bfv[2];
            bfv[0] = *(const unsigned*)&Bs[n][c];
            bfv[1] = *(const unsigned*)&Bs[n][c + 8];
            #pragma unroll
            for (int mi = 0; mi < 4; mi++) {
                int r = mi * 16 + gID;
                unsigned af[4];
                af[0] = *(const unsigned*)&As[r][c];
                af[1] = *(const unsigned*)&As[r + 8][c];
                af[2] = *(const unsigned*)&As[r][c + 8];
                af[3] = *(const unsigned*)&As[r + 8][c + 8];
                mma_bf16(acc[mi], af, bfv);
            }
        }
        __syncthreads();
    }
    float* Cp = C + (size_t)blockIdx.z * 64 * N;
    #pragma unroll
    for (int mi = 0; mi < 4; mi++) {
        int r = mi * 16 + gID;
        int c = col0 + wid * 8 + tig * 2;
        *(float2*)&Cp[(size_t)r * N + c]       = make_float2(acc[mi][0], acc[mi][1]);
        *(float2*)&Cp[(size_t)(r + 8) * N + c] = make_float2(acc[mi][2], acc[mi][3]);
    }
}

// ============ BF16 logits GEMM + fused partial NLL ============================
__global__ __launch_bounds__(256) void gemm_bf16_logits_nll(
    const __nv_bfloat16* __restrict__ A, const __nv_bfloat16* __restrict__ B,
    const float* __restrict__ bias, const int* __restrict__ y, int t, int K) {
    __shared__ __align__(16) unsigned char sbuf[9216 + 36864];
    __nv_bfloat16 (*As)[72] = reinterpret_cast<__nv_bfloat16(*)[72]>(sbuf);
    __nv_bfloat16 (*Bs)[72] = reinterpret_cast<__nv_bfloat16(*)[72]>(sbuf + 9216);
    float (*sm)[8] = reinterpret_cast<float(*)[8]>(sbuf);           // overlays As
    float (*ss)[8] = reinterpret_cast<float(*)[8]>(sbuf + 2048);    // overlays As
    const int col0 = blockIdx.x * 256;
    const int tid = threadIdx.x;
    const int wid = tid >> 5, lane = tid & 31;
    const int gID = lane >> 2, tig = lane & 3;
    const int n0w = wid * 32;
    float acc[4][4][4] = {};
    for (int k0 = 0; k0 < K; k0 += 64) {
        {
            int ar = tid >> 2, as = (tid & 3) * 16;
            *(uint4*)&As[ar][as]     = *(const uint4*)&A[(size_t)ar * K + k0 + as];
            *(uint4*)&As[ar][as + 8] = *(const uint4*)&A[(size_t)ar * K + k0 + as + 8];
            #pragma unroll
            for (int i = 0; i < 8; i++)
                *(uint4*)&Bs[tid][i * 8] = *(const uint4*)&B[(size_t)(col0 + tid) * K + k0 + i * 8];
        }
        __syncthreads();
        #pragma unroll
        for (int kk = 0; kk < 4; kk++) {
            const int kb = kk * 16;
            unsigned af[4][4], bf[4][2];
            #pragma unroll
            for (int mi = 0; mi < 4; mi++) {
                int r = mi * 16 + gID;
                int c = kb + tig * 2;
                af[mi][0] = *(const unsigned*)&As[r][c];
                af[mi][1] = *(const unsigned*)&As[r + 8][c];
                af[mi][2] = *(const unsigned*)&As[r][c + 8];
                af[mi][3] = *(const unsigned*)&As[r + 8][c + 8];
            }
            #pragma unroll
            for (int ni = 0; ni < 4; ni++) {
                int n = n0w + ni * 8 + gID;
                int c = kb + tig * 2;
                bf[ni][0] = *(const unsigned*)&Bs[n][c];
                bf[ni][1] = *(const unsigned*)&Bs[n][c + 8];
            }
            #pragma unroll
            for (int mi = 0; mi < 4; mi++)
                #pragma unroll
                for (int ni = 0; ni < 4; ni++)
                    mma_bf16(acc[mi][ni], af[mi], bf[ni]);
        }
        __syncthreads();
    }
    #pragma unroll
    for (int mi = 0; mi < 4; mi++) {
        const int r  = mi * 16 + gID;
        const int r2 = r + 8;
        const int tgt  = y[(t + 1) * Bn + r];
        const int tgt2 = y[(t + 1) * Bn + r2];
        float m1 = -1e30f, s1 = 0.f, m2 = -1e30f, s2 = 0.f;
        #pragma unroll
        for (int ni = 0; ni < 4; ni++) {
            int c = col0 + n0w + ni * 8 + tig * 2;
            float b0 = bias[c], b1 = bias[c + 1];
            float v0 = acc[mi][ni][0] + b0, v1 = acc[mi][ni][1] + b1;
            float v2 = acc[mi][ni][2] + b0, v3 = acc[mi][ni][3] + b1;
            if (c == tgt)      g_ltgt[r]  = v0;
            if (c + 1 == tgt)  g_ltgt[r]  = v1;
            if (c == tgt2)     g_ltgt[r2] = v2;
            if (c + 1 == tgt2) g_ltgt[r2] = v3;
            lse_upd(m1, s1, v0); lse_upd(m1, s1, v1);
            lse_upd(m2, s2, v2); lse_upd(m2, s2, v3);
        }
        #pragma unroll
        for (int off = 1; off <= 2; off <<= 1) {
            float om = __shfl_xor_sync(0xffffffffu, m1, off);
            float os = __shfl_xor_sync(0xffffffffu, s1, off);
            lse_comb(m1, s1, om, os);
            om = __shfl_xor_sync(0xffffffffu, m2, off);
            os = __shfl_xor_sync(0xffffffffu, s2, off);
            lse_comb(m2, s2, om, os);
        }
        if (tig == 0) {
            sm[r][wid] = m1; ss[r][wid] = s1;
            sm[r2][wid] = m2; ss[r2][wid] = s2;
        }
    }
    __syncthreads();
    if (tid < 64) {
        float M = sm[tid][0], S = ss[tid][0];
        #pragma unroll
        for (int w = 1; w < 8; w++) lse_comb(M, S, sm[tid][w], ss[tid][w]);
        g_pm[blockIdx.x * Bn + tid] = M;
        g_ps[blockIdx.x * Bn + tid] = S;
    }
}

// ============ fused attention + previous step's NLL finalize ==================
__global__ __launch_bounds__(256) void k_att(const float* __restrict__ mlp,
                                             const int* __restrict__ y, int t) {
    const int b = blockIdx.x;
    const int tid = threadIdx.x;
    const int wid = tid >> 5, lane = tid & 31;
    __shared__ float sc[200];
    __shared__ float red[8];
    if (t > 0 && wid == 7) {
        float m = -1e30f, s = 0.f;
        for (int i = lane; i < NVBLK; i += 32)
            lse_comb(m, s, g_pm[i * Bn + b], g_ps[i * Bn + b]);
        #pragma unroll
        for (int off = 16; off; off >>= 1) {
            float om = __shfl_xor_sync(0xffffffffu, m, off);
            float os = __shfl_xor_sync(0xffffffffu, s, off);
            lse_comb(m, s, om, os);
        }
        if (lane == 0) {
            int tgt = y[t * Bn + b];
            g_nll[(t - 1) * Bn + b] = (tgt != 0) ? (m + logf(s) - g_ltgt[b]) : 0.f;
        }
    }
    float hqv[32], mlpv[32];
    #pragma unroll
    for (int j = 0; j < 4; j++) {
        #pragma unroll
        for (int u = 0; u < 8; u++) {
            int m = lane * 8 + j * 256 + u;
            float v = g_hq_part[b * Cdim + m]
                    + g_hq_part[(Bn + b) * Cdim + m]
                    + g_hq_part[(2 * Bn + b) * Cdim + m]
                    + g_hq_part[(3 * Bn + b) * Cdim + m];
            hqv[j * 8 + u] = v;
            mlpv[j * 8 + u] = mlp[m];
        }
    }
    for (int s = wid; s < Sdim; s += 8) {
        const __nv_bfloat16* row = g_ctxp_bf16 + ((size_t)s * Bn + b) * Cdim;
        float sum = 0.f;
        #pragma unroll
        for (int j = 0; j < 4; j++) {
            int m = lane * 8 + j * 256;
            uint4 u = *(const uint4*)&row[m];
            float2 f0 = __bfloat1622float2(*(__nv_bfloat162*)&u.x);
            float2 f1 = __bfloat1622float2(*(__nv_bfloat162*)&u.y);
            float2 f2 = __bfloat1622float2(*(__nv_bfloat162*)&u.z);
            float2 f3 = __bfloat1622float2(*(__nv_bfloat162*)&u.w);
            sum += ftanh_fast(f0.x + hqv[j * 8 + 0]) * mlpv[j * 8 + 0];
            sum += ftanh_fast(f0.y + hqv[j * 8 + 1]) * mlpv[j * 8 + 1];
            sum += ftanh_fast(f1.x + hqv[j * 8 + 2]) * mlpv[j * 8 + 2];
            sum += ftanh_fast(f1.y + hqv[j * 8 + 3]) * mlpv[j * 8 + 3];
            sum += ftanh_fast(f2.x + hqv[j * 8 + 4]) * mlpv[j * 8 + 4];
            sum += ftanh_fast(f2.y + hqv[j * 8 + 5]) * mlpv[j * 8 + 5];
            sum += ftanh_fast(f3.x + hqv[j * 8 + 6]) * mlpv[j * 8 + 6];
            sum += ftanh_fast(f3.y + hqv[j * 8 + 7]) * mlpv[j * 8 + 7];
        }
        #pragma unroll
        for (int o = 16; o; o >>= 1) sum += __shfl_xor_sync(0xffffffffu, sum, o);
        if (lane == 0) sc[s] = sum;
    }
    __syncthreads();
    float v = (tid < Sdim) ? sc[tid] : -1e30f;
    float mx = blockReduceMax(v, red);
    float e = (tid < Sdim) ? __expf(v - mx) : 0.f;
    float tot = blockReduceSum(e, red);
    if (tid < Sdim) sc[tid] = __fdividef(e, tot);
    __syncthreads();
    const int c4 = tid * 4;
    float4 acc = make_float4(0.f, 0.f, 0.f, 0.f);
    #pragma unroll 4
    for (int s = 0; s < Sdim; s++) {
        float a = sc[s];
        uint2 u = *(const uint2*)&g_ctx_bf16[((size_t)s * Bn + b) * Cdim + c4];
        float2 f0 = __bfloat1622float2(*(__nv_bfloat162*)&u.x);
        float2 f1 = __bfloat1622float2(*(__nv_bfloat162*)&u.y);
        acc.x = fmaf(a, f0.x, acc.x); acc.y = fmaf(a, f0.y, acc.y);
        acc.z = fmaf(a, f1.x, acc.z); acc.w = fmaf(a, f1.y, acc.w);
    }
    *(float4*)&g_z[b * Cdim + c4] = acc;
}

// ---------------- per-step elementwise kernels --------------------------------
__global__ void k_gru(const float* __restrict__ b_ih, const float* __restrict__ b_hh) {
    const int i = blockIdx.x * 256 + threadIdx.x;
    const int b = i >> 10, j = i & (Hdim - 1);
    float ir = b_ih[j], iz = b_ih[Hdim + j], in_ = b_ih[2 * Hdim + j];
    #pragma unroll
    for (int p = 0; p < 4; p++) {
        const float* g = g_gi_part + ((size_t)p * Bn + b) * 3 * Hdim;
        ir += g[j]; iz += g[Hdim + j]; in_ += g[2 * Hdim + j];
    }
    float hr = b_hh[j], hz = b_hh[Hdim + j], hn = b_hh[2 * Hdim + j];
    #pragma unroll
    for (int p = 0; p < 4; p++) {
        const float* g = g_gh_part + ((size_t)p * Bn + b) * 3 * Hdim;
        hr += g[j]; hz += g[Hdim + j]; hn += g[2 * Hdim + j];
    }
    float r = fsig(ir + hr);
    float zz = fsig(iz + hz);
    float n = ftanh(in_ + r * hn);
    float hold = g_h[i];
    g_h[i] = (1.f - zz) * n + zz * hold;
}

__global__ void k_pvec(const float* __restrict__ embW, const int* __restrict__ y,
                       const float* __restrict__ h2o_b, const float* __restrict__ octx_b, int t) {
    const int i = blockIdx.x * 256 + threadIdx.x;
    const int b = i >> 9, e = i & (Edim - 1);
    float o1 = h2o_b[e], o2 = octx_b[e];
    #pragma unroll
    for (int p = 0; p < 4; p++) {
        o1 += g_o1_part[p * Bn * Edim + i];
        o2 += g_o2_part[p * Bn * Edim + i];
    }
    float l = ftanh(o1);
    l += embW[(size_t)y[t * Bn + b] * Edim + e];
    l += o2;
    g_p_bf16[i] = __float2bfloat16_rn(ftanh(l));
}

// final: last step's NLL from partials + total sum
__global__ __launch_bounds__(256) void k_final(const int* __restrict__ y, float* __restrict__ out) {
    __shared__ float red[8];
    const int tid = threadIdx.x;
    if (tid < Bn) {
        float m = -1e30f, s = 0.f;
        for (int i = 0; i < NVBLK; i++)
            lse_comb(m, s, g_pm[i * Bn + tid], g_ps[i * Bn + tid]);
        int tgt = y[NSTEP * Bn + tid];
        g_nll[(NSTEP - 1) * Bn + tid] = (tgt != 0) ? (m + logf(s) - g_ltgt[tid]) : 0.f;
    }
    __syncthreads();
    float s = 0.f;
    for (int i = tid; i < NSTEP * Bn; i += 256) s += g_nll[i];
    float tot = blockReduceSum(s, red);
    if (tid == 0) out[0] = tot;
}

// ---------------- launch ------------------------------------------------------
extern "C" void kernel_launch(void* const* d_in, const int* in_sizes, int n_in,
                              void* d_out, int out_size) {
    const float* ctx         = (const float*)d_in[0];
    const int*   y           = (const int*)  d_in[1];
    const float* embW        = (const float*)d_in[2];
    const float* att_ctx2ctx = (const float*)d_in[3];
    const float* att_hid2ctx = (const float*)d_in[4];
    const float* att_mlp     = (const float*)d_in[5];
    const float* gru_W_ih    = (const float*)d_in[6];
    const float* gru_b_ih    = (const float*)d_in[7];
    const float* gru_W_hh    = (const float*)d_in[8];
    const float* gru_b_hh    = (const float*)d_in[9];
    const float* h2o_W       = (const float*)d_in[10];
    const float* h2o_b       = (const float*)d_in[11];
    const float* octx_W      = (const float*)d_in[12];
    const float* octx_b      = (const float*)d_in[13];
    const float* o2p_W       = (const float*)d_in[14];
    const float* o2p_b       = (const float*)d_in[15];

    float *p_h, *p_hqp, *p_z, *p_gip, *p_ghp, *p_o1p, *p_o2p;
    __nv_bfloat16 *p_ctxpbf, *p_ctxbf, *p_WctxTbf, *p_WhidTbf, *p_Wihbf, *p_Whhbf,
                  *p_h2obf, *p_octxbf, *p_Wbf, *p_pbf;
    cudaGetSymbolAddress((void**)&p_ctxpbf,  g_ctxp_bf16);
    cudaGetSymbolAddress((void**)&p_ctxbf,   g_ctx_bf16);
    cudaGetSymbolAddress((void**)&p_WctxTbf, g_WctxT_bf16);
    cudaGetSymbolAddress((void**)&p_WhidTbf, g_WhidT_bf16);
    cudaGetSymbolAddress((void**)&p_Wihbf,   g_Wih_bf16);
    cudaGetSymbolAddress((void**)&p_Whhbf,   g_Whh_bf16);
    cudaGetSymbolAddress((void**)&p_h2obf,   g_h2o_bf16);
    cudaGetSymbolAddress((void**)&p_octxbf,  g_octx_bf16);
    cudaGetSymbolAddress((void**)&p_Wbf,     g_Wo2p_bf16);
    cudaGetSymbolAddress((void**)&p_pbf,     g_p_bf16);
    cudaGetSymbolAddress((void**)&p_h,       g_h);
    cudaGetSymbolAddress((void**)&p_hqp,     g_hq_part);
    cudaGetSymbolAddress((void**)&p_z,       g_z);
    cudaGetSymbolAddress((void**)&p_gip,     g_gi_part);
    cudaGetSymbolAddress((void**)&p_ghp,     g_gh_part);
    cudaGetSymbolAddress((void**)&p_o1p,     g_o1_part);
    cudaGetSymbolAddress((void**)&p_o2p,     g_o2_part);

    // one-time prep
    k_cvt_all<<<(unsigned)((CVT_N5 + 255) / 256), 256>>>(ctx, gru_W_ih, gru_W_hh,
                                                         h2o_W, octx_W, o2p_W);
    k_transpose_bf16<<<dim3(32, 32), dim3(32, 8)>>>(att_ctx2ctx, p_WctxTbf, Cdim, Cdim);
    k_transpose_bf16<<<dim3(32, 32), dim3(32, 8)>>>(att_hid2ctx, p_WhidTbf, Hdim, Cdim);
    k_zero_init<<<(Bn * Hdim + 4 * Bn * Cdim) / 256, 256>>>();
    gemm_bf16_m128<<<dim3(Cdim / 128, (Sdim * Bn) / 128), 256>>>(
        p_ctxbf, p_WctxTbf, p_ctxpbf, Cdim, Cdim);

    for (int t = 0; t < NSTEP; t++) {
        k_att<<<Bn, 256>>>(att_mlp, y, t);
        gemm_bf16_gigh_sk<<<dim3((3 * Hdim) / 64, 2, 4), 256>>>(
            embW, y, t, p_Wihbf, p_gip, p_Whhbf, p_ghp);
        k_gru<<<(Bn * Hdim) / 256, 256>>>(gru_b_ih, gru_b_hh);
        // o1, o2 (this step) + hq (next step) in one launch
        gemm_bf16_m64_tri<<<dim3(Cdim / 64, 3, 4), 256>>>(
            p_h, p_z, p_h2obf, p_octxbf, p_WhidTbf, p_o1p, p_o2p, p_hqp);
        k_pvec<<<(Bn * Edim) / 256, 256>>>(embW, y, h2o_b, octx_b, t);
        gemm_bf16_logits_nll<<<NVBLK, 256>>>(p_pbf, p_Wbf, o2p_b, y, t, Edim);
    }
    k_final<<<1, 256>>>(y, (float*)d_out);
}